// round 8
// baseline (speedup 1.0000x reference)
#include <cuda_runtime.h>
#include <cuda_bf16.h>

#define BATCH 64
#define SEQ   320
#define CH    768
#define HEADS 12
#define HDIM  64
#define KDIM  768
#define MROWS (BATCH*SEQ)   // 20480

// Scratch (device globals: allocation-free rule)
__device__ float g_q[(size_t)BATCH*HEADS*SEQ*HDIM];
__device__ float g_k[(size_t)BATCH*HEADS*SEQ*HDIM];
__device__ float g_v[(size_t)BATCH*HEADS*SEQ*HDIM];
__device__ float g_att[(size_t)BATCH*SEQ*CH];

// ---------------------------------------------------------------------------
// NT SGEMM: C[m][n] = sum_k A[m][k]*W[n][k] + bias[n]
// A: M x 768 row-major, W: N x 768 row-major. BM=BN=128, BK=16, 256 thr, 8x8/thr.
// MODE==1: A = x, epilogue scatters into g_q/g_k/g_v ([B,H,N,D])
// MODE==0: A = g_att, epilogue writes out[m*768+n]
// ---------------------------------------------------------------------------
template<int MODE>
__global__ void __launch_bounds__(256, 2) gemm_nt(const float* __restrict__ Ain,
                                                  const float* __restrict__ W,
                                                  const float* __restrict__ bias,
                                                  float* __restrict__ out)
{
    __shared__ float As[16][128];
    __shared__ float Bs[16][128];

    const float* A = (MODE == 0) ? (const float*)g_att : Ain;
    const int tid = threadIdx.x;
    const int bx = blockIdx.x, by = blockIdx.y;
    const int lrow = tid >> 2;          // 0..63
    const int lk   = (tid & 3) << 2;    // 0,4,8,12
    const int ty = tid >> 4, tx = tid & 15;

    const float* Ag = A + (size_t)(by * 128) * KDIM;
    const float* Wg = W + (size_t)(bx * 128) * KDIM;

    float acc[8][8];
    #pragma unroll
    for (int i = 0; i < 8; i++)
        #pragma unroll
        for (int j = 0; j < 8; j++) acc[i][j] = 0.f;

    // prefetch tile 0
    float4 pa0 = *(const float4*)(Ag + (size_t)lrow * KDIM + lk);
    float4 pa1 = *(const float4*)(Ag + (size_t)(lrow + 64) * KDIM + lk);
    float4 pb0 = *(const float4*)(Wg + (size_t)lrow * KDIM + lk);
    float4 pb1 = *(const float4*)(Wg + (size_t)(lrow + 64) * KDIM + lk);

    const int NT = KDIM / 16;   // 48
    for (int kt = 0; kt < NT; ++kt) {
        As[lk+0][lrow] = pa0.x; As[lk+1][lrow] = pa0.y;
        As[lk+2][lrow] = pa0.z; As[lk+3][lrow] = pa0.w;
        As[lk+0][lrow+64] = pa1.x; As[lk+1][lrow+64] = pa1.y;
        As[lk+2][lrow+64] = pa1.z; As[lk+3][lrow+64] = pa1.w;
        Bs[lk+0][lrow] = pb0.x; Bs[lk+1][lrow] = pb0.y;
        Bs[lk+2][lrow] = pb0.z; Bs[lk+3][lrow] = pb0.w;
        Bs[lk+0][lrow+64] = pb1.x; Bs[lk+1][lrow+64] = pb1.y;
        Bs[lk+2][lrow+64] = pb1.z; Bs[lk+3][lrow+64] = pb1.w;
        __syncthreads();

        if (kt + 1 < NT) {
            const int ko = (kt + 1) * 16 + lk;
            pa0 = *(const float4*)(Ag + (size_t)lrow * KDIM + ko);
            pa1 = *(const float4*)(Ag + (size_t)(lrow + 64) * KDIM + ko);
            pb0 = *(const float4*)(Wg + (size_t)lrow * KDIM + ko);
            pb1 = *(const float4*)(Wg + (size_t)(lrow + 64) * KDIM + ko);
        }

        #pragma unroll
        for (int k = 0; k < 16; ++k) {
            float4 a0 = *(const float4*)&As[k][ty*8];
            float4 a1 = *(const float4*)&As[k][ty*8+4];
            float4 b0 = *(const float4*)&Bs[k][tx*8];
            float4 b1 = *(const float4*)&Bs[k][tx*8+4];
            float ar[8] = {a0.x,a0.y,a0.z,a0.w,a1.x,a1.y,a1.z,a1.w};
            float br[8] = {b0.x,b0.y,b0.z,b0.w,b1.x,b1.y,b1.z,b1.w};
            #pragma unroll
            for (int i = 0; i < 8; i++)
                #pragma unroll
                for (int j = 0; j < 8; j++)
                    acc[i][j] += ar[i] * br[j];
        }
        __syncthreads();
    }

    // epilogue
    float bb[8];
    const int c0 = bx * 128 + tx * 8;
    #pragma unroll
    for (int j = 0; j < 8; j++) bb[j] = bias[c0 + j];

    if (MODE == 0) {
        #pragma unroll
        for (int i = 0; i < 8; i++) {
            const int m = by * 128 + ty * 8 + i;
            float4 v0 = make_float4(acc[i][0]+bb[0], acc[i][1]+bb[1],
                                    acc[i][2]+bb[2], acc[i][3]+bb[3]);
            float4 v1 = make_float4(acc[i][4]+bb[4], acc[i][5]+bb[5],
                                    acc[i][6]+bb[6], acc[i][7]+bb[7]);
            *(float4*)(out + (size_t)m * CH + c0)     = v0;
            *(float4*)(out + (size_t)m * CH + c0 + 4) = v1;
        }
    } else {
        // c0..c0+7 lie within one (which, head) block: 8 | 64 | 768
        const int which = c0 / CH;
        const int wi = c0 - which * CH;
        const int h  = wi >> 6;
        const int d0 = wi & 63;
        float* dst = (which == 0) ? g_q : (which == 1) ? g_k : g_v;
        #pragma unroll
        for (int i = 0; i < 8; i++) {
            const int m = by * 128 + ty * 8 + i;
            const int b = m / SEQ;
            const int n = m - b * SEQ;
            float* p = dst + (((size_t)(b * HEADS + h) * SEQ + n) * HDIM + d0);
            *(float4*)(p)     = make_float4(acc[i][0]+bb[0], acc[i][1]+bb[1],
                                            acc[i][2]+bb[2], acc[i][3]+bb[3]);
            *(float4*)(p + 4) = make_float4(acc[i][4]+bb[4], acc[i][5]+bb[5],
                                            acc[i][6]+bb[6], acc[i][7]+bb[7]);
        }
    }
}

// ---------------------------------------------------------------------------
// Flash-style attention. Block = (qt, h, b); 64 q-rows per block, D=64.
// qt==0: t-window (kv rows [0,64)); qt>=1: s-window (kv rows [0,320), 5 chunks).
// 256 threads as 16x16; each thread owns a 4x4 tile of S / O.
// Smem: Qt [d][q], KP [d][kv] (reused as P [q][kv]), Vs [kv][d] = 48 KB.
// ---------------------------------------------------------------------------
__global__ void __launch_bounds__(256) attn_kernel()
{
    __shared__ float Qt[64 * 64];
    __shared__ float KP[64 * 64];
    __shared__ float Vs[64 * 64];

    const int qt = blockIdx.x, h = blockIdx.y, b = blockIdx.z;
    const int tid = threadIdx.x;
    const int ty = tid >> 4, tx = tid & 15;
    const float scale = 0.125f;   // 1/sqrt(64)

    const float* qp = g_q + ((size_t)(b * HEADS + h) * SEQ + qt * 64) * HDIM;
    const float* kp = g_k + ((size_t)(b * HEADS + h) * SEQ) * HDIM;
    const float* vp = g_v + ((size_t)(b * HEADS + h) * SEQ) * HDIM;

    // Load Q tile transposed: Qt[d][qrow]
    #pragma unroll
    for (int r = 0; r < 4; r++) {
        const int i = tid + 256 * r;
        const int row = i >> 4;
        const int dc = (i & 15) << 2;
        float4 qv = *(const float4*)(qp + row * HDIM + dc);
        Qt[(dc+0)*64 + row] = qv.x;
        Qt[(dc+1)*64 + row] = qv.y;
        Qt[(dc+2)*64 + row] = qv.z;
        Qt[(dc+3)*64 + row] = qv.w;
    }

    float m_[4], l_[4], o_[4][4];
    #pragma unroll
    for (int i = 0; i < 4; i++) {
        m_[i] = -1e30f; l_[i] = 0.f;
        #pragma unroll
        for (int j = 0; j < 4; j++) o_[i][j] = 0.f;
    }

    const int nchunk = (qt == 0) ? 1 : 5;
    for (int c = 0; c < nchunk; ++c) {
        __syncthreads();   // previous chunk's O-gemm done before overwrite

        // Load K chunk transposed (KP[d][kv]) and V chunk natural (Vs[kv][d])
        #pragma unroll
        for (int r = 0; r < 4; r++) {
            const int i = tid + 256 * r;
            const int row = i >> 4;
            const int dc = (i & 15) << 2;
            float4 kv = *(const float4*)(kp + (size_t)(c * 64 + row) * HDIM + dc);
            KP[(dc+0)*64 + row] = kv.x;
            KP[(dc+1)*64 + row] = kv.y;
            KP[(dc+2)*64 + row] = kv.z;
            KP[(dc+3)*64 + row] = kv.w;
            float4 vv = *(const float4*)(vp + (size_t)(c * 64 + row) * HDIM + dc);
            *(float4*)&Vs[row * 64 + dc] = vv;
        }
        __syncthreads();

        // S = Q K^T (4x4 per thread), conflict-free float4 smem reads
        float s[4][4];
        #pragma unroll
        for (int i = 0; i < 4; i++)
            #pragma unroll
            for (int j = 0; j < 4; j++) s[i][j] = 0.f;

        #pragma unroll 8
        for (int d = 0; d < 64; ++d) {
            float4 q4 = *(const float4*)&Qt[d*64 + ty*4];
            float4 k4 = *(const float4*)&KP[d*64 + tx*4];
            float qa[4] = {q4.x, q4.y, q4.z, q4.w};
            float ka[4] = {k4.x, k4.y, k4.z, k4.w};
            #pragma unroll
            for (int i = 0; i < 4; i++)
                #pragma unroll
                for (int j = 0; j < 4; j++)
                    s[i][j] += qa[i] * ka[j];
        }

        // online softmax (row groups of 16 lanes; xor<=8 stays in-group)
        #pragma unroll
        for (int i = 0; i < 4; i++) {
            #pragma unroll
            for (int j = 0; j < 4; j++) s[i][j] *= scale;
            float mx = fmaxf(fmaxf(s[i][0], s[i][1]), fmaxf(s[i][2], s[i][3]));
            #pragma unroll
            for (int off = 8; off; off >>= 1)
                mx = fmaxf(mx, __shfl_xor_sync(0xffffffffu, mx, off));
            const float mn = fmaxf(m_[i], mx);
            const float corr = __expf(m_[i] - mn);
            float ps = 0.f;
            #pragma unroll
            for (int j = 0; j < 4; j++) {
                s[i][j] = __expf(s[i][j] - mn);
                ps += s[i][j];
            }
            #pragma unroll
            for (int off = 8; off; off >>= 1)
                ps += __shfl_xor_sync(0xffffffffu, ps, off);
            l_[i] = l_[i] * corr + ps;
            m_[i] = mn;
            #pragma unroll
            for (int j = 0; j < 4; j++) o_[i][j] *= corr;
        }

        __syncthreads();   // all threads finished reading KP as K
        #pragma unroll
        for (int i = 0; i < 4; i++)
            *(float4*)&KP[(ty*4 + i) * 64 + tx*4] =
                make_float4(s[i][0], s[i][1], s[i][2], s[i][3]);
        __syncthreads();

        // O += P V
        #pragma unroll 8
        for (int kk = 0; kk < 64; ++kk) {
            float4 v4 = *(const float4*)&Vs[kk*64 + tx*4];
            float va[4] = {v4.x, v4.y, v4.z, v4.w};
            #pragma unroll
            for (int i = 0; i < 4; i++) {
                const float p = KP[(ty*4 + i) * 64 + kk];
                #pragma unroll
                for (int j = 0; j < 4; j++)
                    o_[i][j] += p * va[j];
            }
        }
    }

    // normalize + write to g_att in [B, N, H*D] layout
    #pragma unroll
    for (int i = 0; i < 4; i++) {
        const float inv = 1.0f / l_[i];
        const int n = qt * 64 + ty * 4 + i;
        *(float4*)&g_att[((size_t)b * SEQ + n) * CH + h * HDIM + tx * 4] =
            make_float4(o_[i][0]*inv, o_[i][1]*inv, o_[i][2]*inv, o_[i][3]*inv);
    }
}

// ---------------------------------------------------------------------------
extern "C" void kernel_launch(void* const* d_in, const int* in_sizes, int n_in,
                              void* d_out, int out_size)
{
    const float* x      = (const float*)d_in[0];
    const float* w_qkv  = (const float*)d_in[1];
    const float* b_qkv  = (const float*)d_in[2];
    const float* w_proj = (const float*)d_in[3];
    const float* b_proj = (const float*)d_in[4];
    float* out = (float*)d_out;
    (void)in_sizes; (void)n_in; (void)out_size;

    dim3 gQKV(3 * CH / 128, MROWS / 128);   // 18 x 160
    gemm_nt<1><<<gQKV, 256>>>(x, w_qkv, b_qkv, nullptr);

    dim3 gAtt(5, HEADS, BATCH);             // 5 q-tiles x 12 heads x 64 batch
    attn_kernel<<<gAtt, 256>>>();

    dim3 gProj(CH / 128, MROWS / 128);      // 6 x 160
    gemm_nt<0><<<gProj, 256>>>(nullptr, w_proj, b_proj, out);
}

// round 11
// speedup vs baseline: 1.9016x; 1.9016x over previous
#include <cuda_runtime.h>
#include <cuda_bf16.h>
#include <cstdint>

#define BATCH 64
#define SEQ   320
#define CH    768
#define HEADS 12
#define HDIM  64
#define KDIM  768
#define MROWS (BATCH*SEQ)   // 20480

// ---------------- device global scratch (allocation-free rule) --------------
__device__ float g_q[(size_t)MROWS*CH];
__device__ float g_k[(size_t)MROWS*CH];
__device__ float g_v[(size_t)MROWS*CH];
__device__ __nv_bfloat16 g_xhi[(size_t)MROWS*KDIM];
__device__ __nv_bfloat16 g_xlo[(size_t)MROWS*KDIM];
__device__ __nv_bfloat16 g_wqkv_hi[(size_t)3*CH*KDIM];
__device__ __nv_bfloat16 g_wqkv_lo[(size_t)3*CH*KDIM];
__device__ __nv_bfloat16 g_wproj_hi[(size_t)CH*KDIM];
__device__ __nv_bfloat16 g_wproj_lo[(size_t)CH*KDIM];
__device__ __nv_bfloat16 g_att_hi[(size_t)MROWS*CH];
__device__ __nv_bfloat16 g_att_lo[(size_t)MROWS*CH];

// ---------------- helpers ---------------------------------------------------
__device__ __forceinline__ uint32_t smem_u32(const void* p) {
    uint32_t a;
    asm("{ .reg .u64 t; cvta.to.shared.u64 t, %1; cvt.u32.u64 %0, t; }"
        : "=r"(a) : "l"(p));
    return a;
}
__device__ __forceinline__ void ldmx4(uint32_t* r, uint32_t addr) {
    asm volatile("ldmatrix.sync.aligned.m8n8.x4.shared.b16 {%0,%1,%2,%3}, [%4];"
        : "=r"(r[0]), "=r"(r[1]), "=r"(r[2]), "=r"(r[3]) : "r"(addr));
}
__device__ __forceinline__ void mma16816(float* c, const uint32_t* a,
                                         uint32_t b0, uint32_t b1) {
    asm volatile("mma.sync.aligned.m16n8k16.row.col.f32.bf16.bf16.f32 "
        "{%0,%1,%2,%3}, {%4,%5,%6,%7}, {%8,%9}, {%0,%1,%2,%3};"
        : "+f"(c[0]), "+f"(c[1]), "+f"(c[2]), "+f"(c[3])
        : "r"(a[0]), "r"(a[1]), "r"(a[2]), "r"(a[3]), "r"(b0), "r"(b1));
}
__device__ __forceinline__ uint32_t pack_bf2(__nv_bfloat16 a, __nv_bfloat16 b) {
    return ((uint32_t)__bfloat16_as_ushort(b) << 16) | (uint32_t)__bfloat16_as_ushort(a);
}

// ---------------- fp32 -> bf16 hi/lo split ----------------------------------
template<int T>
__global__ void cvt_split(const float* __restrict__ s, int n4) {
    __nv_bfloat16* hi = (T == 0) ? g_xhi : (T == 1) ? g_wqkv_hi : g_wproj_hi;
    __nv_bfloat16* lo = (T == 0) ? g_xlo : (T == 1) ? g_wqkv_lo : g_wproj_lo;
    int i = blockIdx.x * blockDim.x + threadIdx.x;
    if (i >= n4) return;
    float4 v = ((const float4*)s)[i];
    __nv_bfloat16 h0 = __float2bfloat16(v.x), h1 = __float2bfloat16(v.y);
    __nv_bfloat16 h2 = __float2bfloat16(v.z), h3 = __float2bfloat16(v.w);
    ((uint2*)hi)[i] = make_uint2(pack_bf2(h0, h1), pack_bf2(h2, h3));
    __nv_bfloat16 l0 = __float2bfloat16(v.x - __bfloat162float(h0));
    __nv_bfloat16 l1 = __float2bfloat16(v.y - __bfloat162float(h1));
    __nv_bfloat16 l2 = __float2bfloat16(v.z - __bfloat162float(h2));
    __nv_bfloat16 l3 = __float2bfloat16(v.w - __bfloat162float(h3));
    ((uint2*)lo)[i] = make_uint2(pack_bf2(l0, l1), pack_bf2(l2, l3));
}

// ---------------------------------------------------------------------------
// bf16-split warp-MMA GEMM: C[m][n] = A[m][:] . W[n][:] + bias[n]
// 128x128 tile / CTA, 256 thr (8 warps, 4m x 2n), warp tile 32x64.
// BK=32 bf16 per chunk, 24 chunks, double-buffered cp.async.
// Products: Ah*Bh + Al*Bh + Ah*Bl  (fp32 accum in registers).
// MODE 1: A=x(split), W=wqkv(split), scatter -> g_q/g_k/g_v.
// MODE 0: A=att(split), W=wproj(split), out[m*CH+n].
// ---------------------------------------------------------------------------
#define RSTRIDE 40                      // bf16 units per row (32 + 8 pad)
#define TILE_B  (128*RSTRIDE*2)         // 10240 B per 128x32 tile
#define STAGE_B (4*TILE_B)              // Ah,Al,Bh,Bl = 40960 B
#define SMEM_DYN (2*STAGE_B)            // 81920 B

template<int MODE>
__global__ void __launch_bounds__(256, 2)
gemm_mma(const float* __restrict__ bias, float* __restrict__ out)
{
    extern __shared__ char dsm[];
    __shared__ float sbias[128];

    const __nv_bfloat16* Ahi = (MODE == 1) ? g_xhi : g_att_hi;
    const __nv_bfloat16* Alo = (MODE == 1) ? g_xlo : g_att_lo;
    const __nv_bfloat16* Whi = (MODE == 1) ? g_wqkv_hi : g_wproj_hi;
    const __nv_bfloat16* Wlo = (MODE == 1) ? g_wqkv_lo : g_wproj_lo;

    const int tid = threadIdx.x;
    const int wid = tid >> 5, l = tid & 31;
    const int bx = blockIdx.x, by = blockIdx.y;
    const int warp_m = wid & 3, warp_n = wid >> 2;

    if (tid < 128) sbias[tid] = bias[bx * 128 + tid];

    const uint32_t sb0 = smem_u32(dsm);

    // cp.async loader: 8 x 16B per thread per chunk
    const int lrow = tid >> 2, lseg = tid & 3;
    const __nv_bfloat16* srcs[4] = { Ahi, Alo, Whi, Wlo };
    const int rb_a = by * 128, rb_b = bx * 128;

    auto load_chunk = [&](int c, uint32_t sb) {
        #pragma unroll
        for (int t = 0; t < 4; ++t) {
            const __nv_bfloat16* src = srcs[t];
            const int rowbase = (t < 2) ? rb_a : rb_b;
            #pragma unroll
            for (int p = 0; p < 2; ++p) {
                const int r = lrow + p * 64;
                const void* gp = src + (size_t)(rowbase + r) * KDIM + c * 32 + lseg * 8;
                uint32_t sp = sb + t * TILE_B + (r * RSTRIDE + lseg * 8) * 2;
                asm volatile("cp.async.cg.shared.global [%0], [%1], 16;"
                             :: "r"(sp), "l"(gp) : "memory");
            }
        }
        asm volatile("cp.async.commit_group;" ::: "memory");
    };

    float acc[2][8][4];
    #pragma unroll
    for (int i = 0; i < 2; i++)
        #pragma unroll
        for (int j = 0; j < 8; j++)
            #pragma unroll
            for (int k = 0; k < 4; k++) acc[i][j][k] = 0.f;

    // ldmatrix per-lane address components (bf16 units before *2)
    const int lm = l & 15, lkh = (l >> 4) * 8;
    const uint32_t a_off = ((warp_m * 32 + lm) * RSTRIDE + lkh) * 2;
    const uint32_t b_off = ((warp_n * 64 + lm) * RSTRIDE + lkh) * 2;

    load_chunk(0, sb0);

    const int NC = KDIM / 32;   // 24
    for (int c = 0; c < NC; ++c) {
        if (c + 1 < NC) {
            load_chunk(c + 1, sb0 + ((c + 1) & 1) * STAGE_B);
            asm volatile("cp.async.wait_group 1;" ::: "memory");
        } else {
            asm volatile("cp.async.wait_group 0;" ::: "memory");
        }
        __syncthreads();

        const uint32_t sb = sb0 + (c & 1) * STAGE_B;
        #pragma unroll
        for (int ks = 0; ks < 2; ++ks) {
            const uint32_t koff = ks * 32;   // 16 bf16 = 32 B
            uint32_t ah[2][4], al[2][4], bb[4][4];
            #pragma unroll
            for (int mf = 0; mf < 2; ++mf) {
                ldmx4(ah[mf], sb + a_off + mf * (16 * RSTRIDE * 2) + koff);
                ldmx4(al[mf], sb + TILE_B + a_off + mf * (16 * RSTRIDE * 2) + koff);
            }
            // Bh: hh + lh products
            #pragma unroll
            for (int np = 0; np < 4; ++np)
                ldmx4(bb[np], sb + 2 * TILE_B + b_off + np * (16 * RSTRIDE * 2) + koff);
            #pragma unroll
            for (int mf = 0; mf < 2; ++mf)
                #pragma unroll
                for (int np = 0; np < 4; ++np) {
                    mma16816(acc[mf][2*np],   ah[mf], bb[np][0], bb[np][2]);
                    mma16816(acc[mf][2*np+1], ah[mf], bb[np][1], bb[np][3]);
                    mma16816(acc[mf][2*np],   al[mf], bb[np][0], bb[np][2]);
                    mma16816(acc[mf][2*np+1], al[mf], bb[np][1], bb[np][3]);
                }
            // Bl: hl product (reuse bb regs)
            #pragma unroll
            for (int np = 0; np < 4; ++np)
                ldmx4(bb[np], sb + 3 * TILE_B + b_off + np * (16 * RSTRIDE * 2) + koff);
            #pragma unroll
            for (int mf = 0; mf < 2; ++mf)
                #pragma unroll
                for (int np = 0; np < 4; ++np) {
                    mma16816(acc[mf][2*np],   ah[mf], bb[np][0], bb[np][2]);
                    mma16816(acc[mf][2*np+1], ah[mf], bb[np][1], bb[np][3]);
                }
        }
        __syncthreads();
    }

    // ---- epilogue: fragment -> global (float2 stores), + bias -------------
    const int qr = l >> 2, qc = (l & 3) * 2;
    #pragma unroll
    for (int mf = 0; mf < 2; ++mf) {
        #pragma unroll
        for (int nt = 0; nt < 8; ++nt) {
            const int col = warp_n * 64 + nt * 8 + qc;
            const float b0 = sbias[col], b1 = sbias[col + 1];
            #pragma unroll
            for (int half = 0; half < 2; ++half) {
                const int row = warp_m * 32 + mf * 16 + qr + half * 8;
                float2 v = make_float2(acc[mf][nt][2*half]   + b0,
                                       acc[mf][nt][2*half+1] + b1);
                const int m = by * 128 + row;
                if (MODE == 0) {
                    *(float2*)(out + (size_t)m * CH + bx * 128 + col) = v;
                } else {
                    const int cg = bx * 128 + col;
                    const int which = cg / CH;
                    const int rem = cg - which * CH;
                    const int h = rem >> 6, d0 = rem & 63;
                    const int b = m / SEQ, n = m - b * SEQ;
                    float* dst = (which == 0) ? g_q : (which == 1) ? g_k : g_v;
                    *(float2*)(dst + ((size_t)(b * HEADS + h) * SEQ + n) * HDIM + d0) = v;
                }
            }
        }
    }
}

// ---------------------------------------------------------------------------
// Flash-style attention (fp32 math, proven correct); epilogue writes bf16
// hi/lo into g_att_hi / g_att_lo for the proj GEMM.
// ---------------------------------------------------------------------------
__global__ void __launch_bounds__(256) attn_kernel()
{
    __shared__ float Qt[64 * 64];
    __shared__ float KP[64 * 64];
    __shared__ float Vs[64 * 64];

    const int qt = blockIdx.x, h = blockIdx.y, b = blockIdx.z;
    const int tid = threadIdx.x;
    const int ty = tid >> 4, tx = tid & 15;
    const float scale = 0.125f;

    const float* qp = g_q + ((size_t)(b * HEADS + h) * SEQ + qt * 64) * HDIM;
    const float* kp = g_k + ((size_t)(b * HEADS + h) * SEQ) * HDIM;
    const float* vp = g_v + ((size_t)(b * HEADS + h) * SEQ) * HDIM;

    #pragma unroll
    for (int r = 0; r < 4; r++) {
        const int i = tid + 256 * r;
        const int row = i >> 4;
        const int dc = (i & 15) << 2;
        float4 qv = *(const float4*)(qp + row * HDIM + dc);
        Qt[(dc+0)*64 + row] = qv.x;
        Qt[(dc+1)*64 + row] = qv.y;
        Qt[(dc+2)*64 + row] = qv.z;
        Qt[(dc+3)*64 + row] = qv.w;
    }

    float m_[4], l_[4], o_[4][4];
    #pragma unroll
    for (int i = 0; i < 4; i++) {
        m_[i] = -1e30f; l_[i] = 0.f;
        #pragma unroll
        for (int j = 0; j < 4; j++) o_[i][j] = 0.f;
    }

    const int nchunk = (qt == 0) ? 1 : 5;
    for (int c = 0; c < nchunk; ++c) {
        __syncthreads();
        #pragma unroll
        for (int r = 0; r < 4; r++) {
            const int i = tid + 256 * r;
            const int row = i >> 4;
            const int dc = (i & 15) << 2;
            float4 kv = *(const float4*)(kp + (size_t)(c * 64 + row) * HDIM + dc);
            KP[(dc+0)*64 + row] = kv.x;
            KP[(dc+1)*64 + row] = kv.y;
            KP[(dc+2)*64 + row] = kv.z;
            KP[(dc+3)*64 + row] = kv.w;
            float4 vv = *(const float4*)(vp + (size_t)(c * 64 + row) * HDIM + dc);
            *(float4*)&Vs[row * 64 + dc] = vv;
        }
        __syncthreads();

        float s[4][4];
        #pragma unroll
        for (int i = 0; i < 4; i++)
            #pragma unroll
            for (int j = 0; j < 4; j++) s[i][j] = 0.f;

        #pragma unroll 8
        for (int d = 0; d < 64; ++d) {
            float4 q4 = *(const float4*)&Qt[d*64 + ty*4];
            float4 k4 = *(const float4*)&KP[d*64 + tx*4];
            float qa[4] = {q4.x, q4.y, q4.z, q4.w};
            float ka[4] = {k4.x, k4.y, k4.z, k4.w};
            #pragma unroll
            for (int i = 0; i < 4; i++)
                #pragma unroll
                for (int j = 0; j < 4; j++)
                    s[i][j] += qa[i] * ka[j];
        }

        #pragma unroll
        for (int i = 0; i < 4; i++) {
            #pragma unroll
            for (int j = 0; j < 4; j++) s[i][j] *= scale;
            float mx = fmaxf(fmaxf(s[i][0], s[i][1]), fmaxf(s[i][2], s[i][3]));
            #pragma unroll
            for (int off = 8; off; off >>= 1)
                mx = fmaxf(mx, __shfl_xor_sync(0xffffffffu, mx, off));
            const float mn = fmaxf(m_[i], mx);
            const float corr = __expf(m_[i] - mn);
            float ps = 0.f;
            #pragma unroll
            for (int j = 0; j < 4; j++) {
                s[i][j] = __expf(s[i][j] - mn);
                ps += s[i][j];
            }
            #pragma unroll
            for (int off = 8; off; off >>= 1)
                ps += __shfl_xor_sync(0xffffffffu, ps, off);
            l_[i] = l_[i] * corr + ps;
            m_[i] = mn;
            #pragma unroll
            for (int j = 0; j < 4; j++) o_[i][j] *= corr;
        }

        __syncthreads();
        #pragma unroll
        for (int i = 0; i < 4; i++)
            *(float4*)&KP[(ty*4 + i) * 64 + tx*4] =
                make_float4(s[i][0], s[i][1], s[i][2], s[i][3]);
        __syncthreads();

        #pragma unroll 8
        for (int kk = 0; kk < 64; ++kk) {
            float4 v4 = *(const float4*)&Vs[kk*64 + tx*4];
            float va[4] = {v4.x, v4.y, v4.z, v4.w};
            #pragma unroll
            for (int i = 0; i < 4; i++) {
                const float p = KP[(ty*4 + i) * 64 + kk];
                #pragma unroll
                for (int j = 0; j < 4; j++)
                    o_[i][j] += p * va[j];
            }
        }
    }

    #pragma unroll
    for (int i = 0; i < 4; i++) {
        const float inv = 1.0f / l_[i];
        const int n = qt * 64 + ty * 4 + i;
        const size_t base = ((size_t)b * SEQ + n) * CH + h * HDIM + tx * 4;
        float v0 = o_[i][0]*inv, v1 = o_[i][1]*inv, v2 = o_[i][2]*inv, v3 = o_[i][3]*inv;
        __nv_bfloat16 h0 = __float2bfloat16(v0), h1 = __float2bfloat16(v1);
        __nv_bfloat16 h2 = __float2bfloat16(v2), h3 = __float2bfloat16(v3);
        *(uint2*)(g_att_hi + base) = make_uint2(pack_bf2(h0, h1), pack_bf2(h2, h3));
        __nv_bfloat16 l0 = __float2bfloat16(v0 - __bfloat162float(h0));
        __nv_bfloat16 l1 = __float2bfloat16(v1 - __bfloat162float(h1));
        __nv_bfloat16 l2 = __float2bfloat16(v2 - __bfloat162float(h2));
        __nv_bfloat16 l3 = __float2bfloat16(v3 - __bfloat162float(h3));
        *(uint2*)(g_att_lo + base) = make_uint2(pack_bf2(l0, l1), pack_bf2(l2, l3));
    }
}

// ---------------------------------------------------------------------------
extern "C" void kernel_launch(void* const* d_in, const int* in_sizes, int n_in,
                              void* d_out, int out_size)
{
    const float* x      = (const float*)d_in[0];
    const float* w_qkv  = (const float*)d_in[1];
    const float* b_qkv  = (const float*)d_in[2];
    const float* w_proj = (const float*)d_in[3];
    const float* b_proj = (const float*)d_in[4];
    float* out = (float*)d_out;
    (void)in_sizes; (void)n_in; (void)out_size;

    cudaFuncSetAttribute(gemm_mma<1>, cudaFuncAttributeMaxDynamicSharedMemorySize, SMEM_DYN);
    cudaFuncSetAttribute(gemm_mma<0>, cudaFuncAttributeMaxDynamicSharedMemorySize, SMEM_DYN);

    {   // fp32 -> bf16 hi/lo splits
        int n4 = MROWS * KDIM / 4;
        cvt_split<0><<<(n4 + 255) / 256, 256>>>(x, n4);
        n4 = 3 * CH * KDIM / 4;
        cvt_split<1><<<(n4 + 255) / 256, 256>>>(w_qkv, n4);
        n4 = CH * KDIM / 4;
        cvt_split<2><<<(n4 + 255) / 256, 256>>>(w_proj, n4);
    }

    gemm_mma<1><<<dim3(3 * CH / 128, MROWS / 128), 256, SMEM_DYN>>>(b_qkv, nullptr);
    attn_kernel<<<dim3(5, HEADS, BATCH), 256>>>();
    gemm_mma<0><<<dim3(CH / 128, MROWS / 128), 256, SMEM_DYN>>>(b_proj, out);
}

// round 12
// speedup vs baseline: 2.5401x; 1.3358x over previous
#include <cuda_runtime.h>
#include <cuda_bf16.h>
#include <cstdint>

#define BATCH 64
#define SEQ   320
#define CH    768
#define HEADS 12
#define HDIM  64
#define KDIM  768
#define MROWS (BATCH*SEQ)   // 20480

// ---------------- device global scratch (allocation-free rule) --------------
__device__ __nv_bfloat16 g_qh[(size_t)BATCH*HEADS*SEQ*HDIM];
__device__ __nv_bfloat16 g_ql[(size_t)BATCH*HEADS*SEQ*HDIM];
__device__ __nv_bfloat16 g_kh[(size_t)BATCH*HEADS*SEQ*HDIM];
__device__ __nv_bfloat16 g_kl[(size_t)BATCH*HEADS*SEQ*HDIM];
__device__ __nv_bfloat16 g_vh[(size_t)BATCH*HEADS*SEQ*HDIM];
__device__ __nv_bfloat16 g_vl[(size_t)BATCH*HEADS*SEQ*HDIM];
__device__ __nv_bfloat16 g_xhi[(size_t)MROWS*KDIM];
__device__ __nv_bfloat16 g_xlo[(size_t)MROWS*KDIM];
__device__ __nv_bfloat16 g_wqkv_hi[(size_t)3*CH*KDIM];
__device__ __nv_bfloat16 g_wqkv_lo[(size_t)3*CH*KDIM];
__device__ __nv_bfloat16 g_wproj_hi[(size_t)CH*KDIM];
__device__ __nv_bfloat16 g_wproj_lo[(size_t)CH*KDIM];
__device__ __nv_bfloat16 g_att_hi[(size_t)MROWS*CH];
__device__ __nv_bfloat16 g_att_lo[(size_t)MROWS*CH];

// ---------------- helpers ---------------------------------------------------
__device__ __forceinline__ uint32_t smem_u32(const void* p) {
    uint32_t a;
    asm("{ .reg .u64 t; cvta.to.shared.u64 t, %1; cvt.u32.u64 %0, t; }"
        : "=r"(a) : "l"(p));
    return a;
}
__device__ __forceinline__ void ldmx4(uint32_t* r, uint32_t addr) {
    asm volatile("ldmatrix.sync.aligned.m8n8.x4.shared.b16 {%0,%1,%2,%3}, [%4];"
        : "=r"(r[0]), "=r"(r[1]), "=r"(r[2]), "=r"(r[3]) : "r"(addr));
}
__device__ __forceinline__ void ldmx4t(uint32_t* r, uint32_t addr) {
    asm volatile("ldmatrix.sync.aligned.m8n8.x4.trans.shared.b16 {%0,%1,%2,%3}, [%4];"
        : "=r"(r[0]), "=r"(r[1]), "=r"(r[2]), "=r"(r[3]) : "r"(addr));
}
__device__ __forceinline__ void mma16816(float* c, const uint32_t* a,
                                         uint32_t b0, uint32_t b1) {
    asm volatile("mma.sync.aligned.m16n8k16.row.col.f32.bf16.bf16.f32 "
        "{%0,%1,%2,%3}, {%4,%5,%6,%7}, {%8,%9}, {%0,%1,%2,%3};"
        : "+f"(c[0]), "+f"(c[1]), "+f"(c[2]), "+f"(c[3])
        : "r"(a[0]), "r"(a[1]), "r"(a[2]), "r"(a[3]), "r"(b0), "r"(b1));
}
__device__ __forceinline__ uint32_t pack_bf2(__nv_bfloat16 a, __nv_bfloat16 b) {
    return ((uint32_t)__bfloat16_as_ushort(b) << 16) | (uint32_t)__bfloat16_as_ushort(a);
}
__device__ __forceinline__ void split2(float x, float y, uint32_t& hi, uint32_t& lo) {
    __nv_bfloat16 hx = __float2bfloat16(x), hy = __float2bfloat16(y);
    hi = pack_bf2(hx, hy);
    lo = pack_bf2(__float2bfloat16(x - __bfloat162float(hx)),
                  __float2bfloat16(y - __bfloat162float(hy)));
}

// ---------------- fp32 -> bf16 hi/lo split ----------------------------------
template<int T>
__global__ void cvt_split(const float* __restrict__ s, int n4) {
    __nv_bfloat16* hi = (T == 0) ? g_xhi : (T == 1) ? g_wqkv_hi : g_wproj_hi;
    __nv_bfloat16* lo = (T == 0) ? g_xlo : (T == 1) ? g_wqkv_lo : g_wproj_lo;
    int i = blockIdx.x * blockDim.x + threadIdx.x;
    if (i >= n4) return;
    float4 v = ((const float4*)s)[i];
    uint32_t h0, l0, h1, l1;
    split2(v.x, v.y, h0, l0);
    split2(v.z, v.w, h1, l1);
    ((uint2*)hi)[i] = make_uint2(h0, h1);
    ((uint2*)lo)[i] = make_uint2(l0, l1);
}

// ---------------------------------------------------------------------------
// bf16-split warp-MMA GEMM (unchanged core from the 1481us kernel).
// MODE 1: A=x(split), W=wqkv(split), epilogue SPLITS to bf16 -> g_{q,k,v}{h,l}.
// MODE 0: A=att(split), W=wproj(split), out[m*CH+n] fp32.
// ---------------------------------------------------------------------------
#define RSTRIDE 40
#define TILE_B  (128*RSTRIDE*2)
#define STAGE_B (4*TILE_B)
#define SMEM_DYN (2*STAGE_B)

template<int MODE>
__global__ void __launch_bounds__(256, 2)
gemm_mma(const float* __restrict__ bias, float* __restrict__ out)
{
    extern __shared__ char dsm[];
    __shared__ float sbias[128];

    const __nv_bfloat16* Ahi = (MODE == 1) ? g_xhi : g_att_hi;
    const __nv_bfloat16* Alo = (MODE == 1) ? g_xlo : g_att_lo;
    const __nv_bfloat16* Whi = (MODE == 1) ? g_wqkv_hi : g_wproj_hi;
    const __nv_bfloat16* Wlo = (MODE == 1) ? g_wqkv_lo : g_wproj_lo;

    const int tid = threadIdx.x;
    const int wid = tid >> 5, l = tid & 31;
    const int bx = blockIdx.x, by = blockIdx.y;
    const int warp_m = wid & 3, warp_n = wid >> 2;

    if (tid < 128) sbias[tid] = bias[bx * 128 + tid];

    const uint32_t sb0 = smem_u32(dsm);
    const int lrow = tid >> 2, lseg = tid & 3;
    const __nv_bfloat16* srcs[4] = { Ahi, Alo, Whi, Wlo };
    const int rb_a = by * 128, rb_b = bx * 128;

    auto load_chunk = [&](int c, uint32_t sb) {
        #pragma unroll
        for (int t = 0; t < 4; ++t) {
            const __nv_bfloat16* src = srcs[t];
            const int rowbase = (t < 2) ? rb_a : rb_b;
            #pragma unroll
            for (int p = 0; p < 2; ++p) {
                const int r = lrow + p * 64;
                const void* gp = src + (size_t)(rowbase + r) * KDIM + c * 32 + lseg * 8;
                uint32_t sp = sb + t * TILE_B + (r * RSTRIDE + lseg * 8) * 2;
                asm volatile("cp.async.cg.shared.global [%0], [%1], 16;"
                             :: "r"(sp), "l"(gp) : "memory");
            }
        }
        asm volatile("cp.async.commit_group;" ::: "memory");
    };

    float acc[2][8][4];
    #pragma unroll
    for (int i = 0; i < 2; i++)
        #pragma unroll
        for (int j = 0; j < 8; j++)
            #pragma unroll
            for (int k = 0; k < 4; k++) acc[i][j][k] = 0.f;

    const int lm = l & 15, lkh = (l >> 4) * 8;
    const uint32_t a_off = ((warp_m * 32 + lm) * RSTRIDE + lkh) * 2;
    const uint32_t b_off = ((warp_n * 64 + lm) * RSTRIDE + lkh) * 2;

    load_chunk(0, sb0);

    const int NC = KDIM / 32;
    for (int c = 0; c < NC; ++c) {
        if (c + 1 < NC) {
            load_chunk(c + 1, sb0 + ((c + 1) & 1) * STAGE_B);
            asm volatile("cp.async.wait_group 1;" ::: "memory");
        } else {
            asm volatile("cp.async.wait_group 0;" ::: "memory");
        }
        __syncthreads();

        const uint32_t sb = sb0 + (c & 1) * STAGE_B;
        #pragma unroll
        for (int ks = 0; ks < 2; ++ks) {
            const uint32_t koff = ks * 32;
            uint32_t ah[2][4], al[2][4], bb[4][4];
            #pragma unroll
            for (int mf = 0; mf < 2; ++mf) {
                ldmx4(ah[mf], sb + a_off + mf * (16 * RSTRIDE * 2) + koff);
                ldmx4(al[mf], sb + TILE_B + a_off + mf * (16 * RSTRIDE * 2) + koff);
            }
            #pragma unroll
            for (int np = 0; np < 4; ++np)
                ldmx4(bb[np], sb + 2 * TILE_B + b_off + np * (16 * RSTRIDE * 2) + koff);
            #pragma unroll
            for (int mf = 0; mf < 2; ++mf)
                #pragma unroll
                for (int np = 0; np < 4; ++np) {
                    mma16816(acc[mf][2*np],   ah[mf], bb[np][0], bb[np][2]);
                    mma16816(acc[mf][2*np+1], ah[mf], bb[np][1], bb[np][3]);
                    mma16816(acc[mf][2*np],   al[mf], bb[np][0], bb[np][2]);
                    mma16816(acc[mf][2*np+1], al[mf], bb[np][1], bb[np][3]);
                }
            #pragma unroll
            for (int np = 0; np < 4; ++np)
                ldmx4(bb[np], sb + 3 * TILE_B + b_off + np * (16 * RSTRIDE * 2) + koff);
            #pragma unroll
            for (int mf = 0; mf < 2; ++mf)
                #pragma unroll
                for (int np = 0; np < 4; ++np) {
                    mma16816(acc[mf][2*np],   ah[mf], bb[np][0], bb[np][2]);
                    mma16816(acc[mf][2*np+1], ah[mf], bb[np][1], bb[np][3]);
                }
        }
        __syncthreads();
    }

    const int qr = l >> 2, qc = (l & 3) * 2;
    #pragma unroll
    for (int mf = 0; mf < 2; ++mf) {
        #pragma unroll
        for (int nt = 0; nt < 8; ++nt) {
            const int col = warp_n * 64 + nt * 8 + qc;
            const float b0 = sbias[col], b1 = sbias[col + 1];
            #pragma unroll
            for (int half = 0; half < 2; ++half) {
                const int row = warp_m * 32 + mf * 16 + qr + half * 8;
                const float vx = acc[mf][nt][2*half] + b0;
                const float vy = acc[mf][nt][2*half+1] + b1;
                const int m = by * 128 + row;
                if (MODE == 0) {
                    *(float2*)(out + (size_t)m * CH + bx * 128 + col) =
                        make_float2(vx, vy);
                } else {
                    const int cg = bx * 128 + col;
                    const int which = cg / CH;
                    const int rem = cg - which * CH;
                    const int h = rem >> 6, d0 = rem & 63;
                    const int b = m / SEQ, n = m - b * SEQ;
                    __nv_bfloat16* dh = (which == 0) ? g_qh : (which == 1) ? g_kh : g_vh;
                    __nv_bfloat16* dl = (which == 0) ? g_ql : (which == 1) ? g_kl : g_vl;
                    const size_t off = ((size_t)(b * HEADS + h) * SEQ + n) * HDIM + d0;
                    uint32_t hi, lo;
                    split2(vx, vy, hi, lo);
                    *(uint32_t*)(dh + off) = hi;
                    *(uint32_t*)(dl + off) = lo;
                }
            }
        }
    }
}

// ---------------------------------------------------------------------------
// Tensor-core flash attention. Block (qt,h,b), 128 thr = 4 warps x 16 q-rows.
// S = QK^T and O = PV via bf16-split mma.sync; softmax in fragment layout.
// Smem: Qh Ql Kh Kl Vh Vl, 64x64 bf16 each, row stride 72 (144 B).
// ---------------------------------------------------------------------------
#define AROW  72
#define ATILE (64*AROW*2)     // 9216 B
#define ASMEM (6*ATILE)       // 55296 B

__global__ void __launch_bounds__(128) attn_mma()
{
    extern __shared__ char smbuf[];
    const uint32_t s0  = smem_u32(smbuf);
    const uint32_t sQh = s0,             sQl = s0 + ATILE;
    const uint32_t sKh = s0 + 2*ATILE,   sKl = s0 + 3*ATILE;
    const uint32_t sVh = s0 + 4*ATILE,   sVl = s0 + 5*ATILE;

    const int qt = blockIdx.x, h = blockIdx.y, b = blockIdx.z;
    const int tid = threadIdx.x;
    const int w = tid >> 5, l = tid & 31;

    const size_t head_off = (size_t)(b * HEADS + h) * SEQ * HDIM;
    const __nv_bfloat16* qhp = g_qh + head_off + (size_t)qt * 64 * HDIM;
    const __nv_bfloat16* qlp = g_ql + head_off + (size_t)qt * 64 * HDIM;
    const __nv_bfloat16* khp = g_kh + head_off;
    const __nv_bfloat16* klp = g_kl + head_off;
    const __nv_bfloat16* vhp = g_vh + head_off;
    const __nv_bfloat16* vlp = g_vl + head_off;

    // --- load Q (once) + KV chunk 0 -------------------------------------
    #pragma unroll
    for (int it = 0; it < 4; ++it) {
        const int idx = tid + 128 * it;
        const int row = idx >> 3, seg = idx & 7;
        const uint32_t sp = row * 144 + seg * 16;
        const size_t gp = (size_t)row * HDIM + seg * 8;
        asm volatile("cp.async.cg.shared.global [%0], [%1], 16;"
                     :: "r"(sQh + sp), "l"(qhp + gp) : "memory");
        asm volatile("cp.async.cg.shared.global [%0], [%1], 16;"
                     :: "r"(sQl + sp), "l"(qlp + gp) : "memory");
    }
    auto load_kv = [&](int c) {
        #pragma unroll
        for (int it = 0; it < 4; ++it) {
            const int idx = tid + 128 * it;
            const int row = idx >> 3, seg = idx & 7;
            const uint32_t sp = row * 144 + seg * 16;
            const size_t gp = (size_t)(c * 64 + row) * HDIM + seg * 8;
            asm volatile("cp.async.cg.shared.global [%0], [%1], 16;"
                         :: "r"(sKh + sp), "l"(khp + gp) : "memory");
            asm volatile("cp.async.cg.shared.global [%0], [%1], 16;"
                         :: "r"(sKl + sp), "l"(klp + gp) : "memory");
            asm volatile("cp.async.cg.shared.global [%0], [%1], 16;"
                         :: "r"(sVh + sp), "l"(vhp + gp) : "memory");
            asm volatile("cp.async.cg.shared.global [%0], [%1], 16;"
                         :: "r"(sVl + sp), "l"(vlp + gp) : "memory");
        }
        asm volatile("cp.async.commit_group;" ::: "memory");
    };
    load_kv(0);
    asm volatile("cp.async.wait_group 0;" ::: "memory");
    __syncthreads();

    // --- Q fragments in registers ---------------------------------------
    const int lm = l & 15, lk8 = (l >> 4) * 8;
    uint32_t qfh[4][4], qfl[4][4];
    #pragma unroll
    for (int ks = 0; ks < 4; ++ks) {
        const uint32_t off = (w * 16 + lm) * 144 + ks * 32 + lk8 * 2;
        ldmx4(qfh[ks], sQh + off);
        ldmx4(qfl[ks], sQl + off);
    }

    float m0 = -1e30f, m1 = -1e30f, l0 = 0.f, l1 = 0.f;
    float oacc[8][4];
    #pragma unroll
    for (int t = 0; t < 8; ++t)
        #pragma unroll
        for (int j = 0; j < 4; ++j) oacc[t][j] = 0.f;

    const int koff_t = ((l >> 3) & 1) * 8 + (l & 7);   // trans-ldmatrix k row
    const int noff_t = ((l >> 4) & 1) * 8;             // trans-ldmatrix n col

    const int nchunk = (qt == 0) ? 1 : 5;
    for (int c = 0; c < nchunk; ++c) {
        if (c > 0) {
            __syncthreads();                 // everyone done reading K/V smem
            load_kv(c);
            asm volatile("cp.async.wait_group 0;" ::: "memory");
            __syncthreads();
        }

        // ---- S = Q K^T (bf16 split, fp32 acc) --------------------------
        float sacc[8][4];
        #pragma unroll
        for (int t = 0; t < 8; ++t)
            #pragma unroll
            for (int j = 0; j < 4; ++j) sacc[t][j] = 0.f;

        #pragma unroll
        for (int ks = 0; ks < 4; ++ks) {
            uint32_t kbh[4][4], kbl[4][4];
            #pragma unroll
            for (int nt = 0; nt < 4; ++nt) {
                const uint32_t off = (nt * 16 + lm) * 144 + ks * 32 + lk8 * 2;
                ldmx4(kbh[nt], sKh + off);
                ldmx4(kbl[nt], sKl + off);
            }
            #pragma unroll
            for (int nt = 0; nt < 4; ++nt) {
                mma16816(sacc[2*nt],   qfh[ks], kbh[nt][0], kbh[nt][2]);
                mma16816(sacc[2*nt+1], qfh[ks], kbh[nt][1], kbh[nt][3]);
                mma16816(sacc[2*nt],   qfl[ks], kbh[nt][0], kbh[nt][2]);
                mma16816(sacc[2*nt+1], qfl[ks], kbh[nt][1], kbh[nt][3]);
                mma16816(sacc[2*nt],   qfh[ks], kbl[nt][0], kbl[nt][2]);
                mma16816(sacc[2*nt+1], qfh[ks], kbl[nt][1], kbl[nt][3]);
            }
        }

        // ---- softmax in fragment layout --------------------------------
        #pragma unroll
        for (int t = 0; t < 8; ++t)
            #pragma unroll
            for (int j = 0; j < 4; ++j) sacc[t][j] *= 0.125f;

        float mx0 = -1e30f, mx1 = -1e30f;
        #pragma unroll
        for (int t = 0; t < 8; ++t) {
            mx0 = fmaxf(mx0, fmaxf(sacc[t][0], sacc[t][1]));
            mx1 = fmaxf(mx1, fmaxf(sacc[t][2], sacc[t][3]));
        }
        mx0 = fmaxf(mx0, __shfl_xor_sync(0xffffffffu, mx0, 1));
        mx0 = fmaxf(mx0, __shfl_xor_sync(0xffffffffu, mx0, 2));
        mx1 = fmaxf(mx1, __shfl_xor_sync(0xffffffffu, mx1, 1));
        mx1 = fmaxf(mx1, __shfl_xor_sync(0xffffffffu, mx1, 2));

        const float mn0 = fmaxf(m0, mx0), mn1 = fmaxf(m1, mx1);
        const float cr0 = __expf(m0 - mn0), cr1 = __expf(m1 - mn1);
        m0 = mn0; m1 = mn1;

        float sm0 = 0.f, sm1 = 0.f;
        #pragma unroll
        for (int t = 0; t < 8; ++t) {
            sacc[t][0] = __expf(sacc[t][0] - mn0);
            sacc[t][1] = __expf(sacc[t][1] - mn0);
            sacc[t][2] = __expf(sacc[t][2] - mn1);
            sacc[t][3] = __expf(sacc[t][3] - mn1);
            sm0 += sacc[t][0] + sacc[t][1];
            sm1 += sacc[t][2] + sacc[t][3];
        }
        sm0 += __shfl_xor_sync(0xffffffffu, sm0, 1);
        sm0 += __shfl_xor_sync(0xffffffffu, sm0, 2);
        sm1 += __shfl_xor_sync(0xffffffffu, sm1, 1);
        sm1 += __shfl_xor_sync(0xffffffffu, sm1, 2);
        l0 = l0 * cr0 + sm0;
        l1 = l1 * cr1 + sm1;

        #pragma unroll
        for (int t = 0; t < 8; ++t) {
            oacc[t][0] *= cr0; oacc[t][1] *= cr0;
            oacc[t][2] *= cr1; oacc[t][3] *= cr1;
        }

        // ---- O += P V (P split in regs, V via ldmatrix.trans) ----------
        #pragma unroll
        for (int ks = 0; ks < 4; ++ks) {
            uint32_t pah[4], pal[4];
            split2(sacc[2*ks][0],   sacc[2*ks][1],   pah[0], pal[0]);
            split2(sacc[2*ks][2],   sacc[2*ks][3],   pah[1], pal[1]);
            split2(sacc[2*ks+1][0], sacc[2*ks+1][1], pah[2], pal[2]);
            split2(sacc[2*ks+1][2], sacc[2*ks+1][3], pah[3], pal[3]);

            uint32_t vbh[4][4], vbl[4][4];
            #pragma unroll
            for (int nd = 0; nd < 4; ++nd) {
                const uint32_t off = (ks * 16 + koff_t) * 144
                                   + (nd * 16 + noff_t) * 2;
                ldmx4t(vbh[nd], sVh + off);
                ldmx4t(vbl[nd], sVl + off);
            }
            #pragma unroll
            for (int nd = 0; nd < 4; ++nd) {
                mma16816(oacc[2*nd],   pah, vbh[nd][0], vbh[nd][1]);
                mma16816(oacc[2*nd+1], pah, vbh[nd][2], vbh[nd][3]);
                mma16816(oacc[2*nd],   pal, vbh[nd][0], vbh[nd][1]);
                mma16816(oacc[2*nd+1], pal, vbh[nd][2], vbh[nd][3]);
                mma16816(oacc[2*nd],   pah, vbl[nd][0], vbl[nd][1]);
                mma16816(oacc[2*nd+1], pah, vbl[nd][2], vbl[nd][3]);
            }
        }
    }

    // ---- normalize + write bf16 hi/lo for proj GEMM ---------------------
    const float inv0 = 1.0f / l0, inv1 = 1.0f / l1;
    const int n0 = qt * 64 + w * 16 + (l >> 2);
    const int n1 = n0 + 8;
    const size_t row0 = ((size_t)b * SEQ + n0) * CH + h * HDIM;
    const size_t row1 = ((size_t)b * SEQ + n1) * CH + h * HDIM;
    #pragma unroll
    for (int t = 0; t < 8; ++t) {
        const int d0 = t * 8 + (l & 3) * 2;
        uint32_t hi, lo;
        split2(oacc[t][0] * inv0, oacc[t][1] * inv0, hi, lo);
        *(uint32_t*)(g_att_hi + row0 + d0) = hi;
        *(uint32_t*)(g_att_lo + row0 + d0) = lo;
        split2(oacc[t][2] * inv1, oacc[t][3] * inv1, hi, lo);
        *(uint32_t*)(g_att_hi + row1 + d0) = hi;
        *(uint32_t*)(g_att_lo + row1 + d0) = lo;
    }
}

// ---------------------------------------------------------------------------
extern "C" void kernel_launch(void* const* d_in, const int* in_sizes, int n_in,
                              void* d_out, int out_size)
{
    const float* x      = (const float*)d_in[0];
    const float* w_qkv  = (const float*)d_in[1];
    const float* b_qkv  = (const float*)d_in[2];
    const float* w_proj = (const float*)d_in[3];
    const float* b_proj = (const float*)d_in[4];
    float* out = (float*)d_out;
    (void)in_sizes; (void)n_in; (void)out_size;

    cudaFuncSetAttribute(gemm_mma<1>, cudaFuncAttributeMaxDynamicSharedMemorySize, SMEM_DYN);
    cudaFuncSetAttribute(gemm_mma<0>, cudaFuncAttributeMaxDynamicSharedMemorySize, SMEM_DYN);
    cudaFuncSetAttribute(attn_mma, cudaFuncAttributeMaxDynamicSharedMemorySize, ASMEM);

    {   // fp32 -> bf16 hi/lo splits
        int n4 = MROWS * KDIM / 4;
        cvt_split<0><<<(n4 + 255) / 256, 256>>>(x, n4);
        n4 = 3 * CH * KDIM / 4;
        cvt_split<1><<<(n4 + 255) / 256, 256>>>(w_qkv, n4);
        n4 = CH * KDIM / 4;
        cvt_split<2><<<(n4 + 255) / 256, 256>>>(w_proj, n4);
    }

    gemm_mma<1><<<dim3(3 * CH / 128, MROWS / 128), 256, SMEM_DYN>>>(b_qkv, nullptr);
    attn_mma<<<dim3(5, HEADS, BATCH), 128, ASMEM>>>();
    gemm_mma<0><<<dim3(CH / 128, MROWS / 128), 256, SMEM_DYN>>>(b_proj, out);
}

// round 13
// speedup vs baseline: 2.5416x; 1.0006x over previous
#include <cuda_runtime.h>
#include <cuda_bf16.h>
#include <cstdint>

#define BATCH 64
#define SEQ   320
#define CH    768
#define HEADS 12
#define HDIM  64
#define KDIM  768
#define MROWS (BATCH*SEQ)   // 20480

// ---------------- device global scratch (allocation-free rule) --------------
__device__ __nv_bfloat16 g_qh[(size_t)BATCH*HEADS*SEQ*HDIM];
__device__ __nv_bfloat16 g_ql[(size_t)BATCH*HEADS*SEQ*HDIM];
__device__ __nv_bfloat16 g_kh[(size_t)BATCH*HEADS*SEQ*HDIM];
__device__ __nv_bfloat16 g_kl[(size_t)BATCH*HEADS*SEQ*HDIM];
__device__ __nv_bfloat16 g_vh[(size_t)BATCH*HEADS*SEQ*HDIM];
__device__ __nv_bfloat16 g_vl[(size_t)BATCH*HEADS*SEQ*HDIM];
__device__ __nv_bfloat16 g_xhi[(size_t)MROWS*KDIM];
__device__ __nv_bfloat16 g_xlo[(size_t)MROWS*KDIM];
__device__ __nv_bfloat16 g_wqkv_hi[(size_t)3*CH*KDIM];
__device__ __nv_bfloat16 g_wqkv_lo[(size_t)3*CH*KDIM];
__device__ __nv_bfloat16 g_wproj_hi[(size_t)CH*KDIM];
__device__ __nv_bfloat16 g_wproj_lo[(size_t)CH*KDIM];
__device__ __nv_bfloat16 g_att_hi[(size_t)MROWS*CH];
__device__ __nv_bfloat16 g_att_lo[(size_t)MROWS*CH];

// ---------------- helpers ---------------------------------------------------
__device__ __forceinline__ uint32_t smem_u32(const void* p) {
    uint32_t a;
    asm("{ .reg .u64 t; cvta.to.shared.u64 t, %1; cvt.u32.u64 %0, t; }"
        : "=r"(a) : "l"(p));
    return a;
}
__device__ __forceinline__ void ldmx4(uint32_t* r, uint32_t addr) {
    asm volatile("ldmatrix.sync.aligned.m8n8.x4.shared.b16 {%0,%1,%2,%3}, [%4];"
        : "=r"(r[0]), "=r"(r[1]), "=r"(r[2]), "=r"(r[3]) : "r"(addr));
}
__device__ __forceinline__ void ldmx4t(uint32_t* r, uint32_t addr) {
    asm volatile("ldmatrix.sync.aligned.m8n8.x4.trans.shared.b16 {%0,%1,%2,%3}, [%4];"
        : "=r"(r[0]), "=r"(r[1]), "=r"(r[2]), "=r"(r[3]) : "r"(addr));
}
__device__ __forceinline__ void mma16816(float* c, const uint32_t* a,
                                         uint32_t b0, uint32_t b1) {
    asm volatile("mma.sync.aligned.m16n8k16.row.col.f32.bf16.bf16.f32 "
        "{%0,%1,%2,%3}, {%4,%5,%6,%7}, {%8,%9}, {%0,%1,%2,%3};"
        : "+f"(c[0]), "+f"(c[1]), "+f"(c[2]), "+f"(c[3])
        : "r"(a[0]), "r"(a[1]), "r"(a[2]), "r"(a[3]), "r"(b0), "r"(b1));
}
__device__ __forceinline__ uint32_t pack_bf2(__nv_bfloat16 a, __nv_bfloat16 b) {
    return ((uint32_t)__bfloat16_as_ushort(b) << 16) | (uint32_t)__bfloat16_as_ushort(a);
}
__device__ __forceinline__ void split2(float x, float y, uint32_t& hi, uint32_t& lo) {
    __nv_bfloat16 hx = __float2bfloat16(x), hy = __float2bfloat16(y);
    hi = pack_bf2(hx, hy);
    lo = pack_bf2(__float2bfloat16(x - __bfloat162float(hx)),
                  __float2bfloat16(y - __bfloat162float(hy)));
}

// ---------------- fp32 -> bf16 hi/lo split ----------------------------------
template<int T>
__global__ void cvt_split(const float* __restrict__ s, int n4) {
    __nv_bfloat16* hi = (T == 0) ? g_xhi : (T == 1) ? g_wqkv_hi : g_wproj_hi;
    __nv_bfloat16* lo = (T == 0) ? g_xlo : (T == 1) ? g_wqkv_lo : g_wproj_lo;
    int i = blockIdx.x * blockDim.x + threadIdx.x;
    if (i >= n4) return;
    float4 v = ((const float4*)s)[i];
    uint32_t h0, l0, h1, l1;
    split2(v.x, v.y, h0, l0);
    split2(v.z, v.w, h1, l1);
    ((uint2*)hi)[i] = make_uint2(h0, h1);
    ((uint2*)lo)[i] = make_uint2(l0, l1);
}

// ---------------------------------------------------------------------------
// bf16-split warp-MMA GEMM. 128x128 tile, 8 warps (4m x 2n), warp tile 32x64.
// BK=32, double-buffered cp.async. MMAs issued in three RAW-free passes:
// hh (16 distinct accs), lh (16), hl (16) -> accumulator reuse distance ~15.
// MODE 1: A=x(split), W=wqkv(split), epilogue splits to bf16 -> g_{q,k,v}{h,l}.
// MODE 0: A=att(split), W=wproj(split), out[m*CH+n] fp32.
// ---------------------------------------------------------------------------
#define RSTRIDE 40
#define TILE_B  (128*RSTRIDE*2)
#define STAGE_B (4*TILE_B)
#define SMEM_DYN (2*STAGE_B)

template<int MODE>
__global__ void __launch_bounds__(256, 2)
gemm_mma(const float* __restrict__ bias, float* __restrict__ out)
{
    extern __shared__ char dsm[];
    __shared__ float sbias[128];

    const __nv_bfloat16* Ahi = (MODE == 1) ? g_xhi : g_att_hi;
    const __nv_bfloat16* Alo = (MODE == 1) ? g_xlo : g_att_lo;
    const __nv_bfloat16* Whi = (MODE == 1) ? g_wqkv_hi : g_wproj_hi;
    const __nv_bfloat16* Wlo = (MODE == 1) ? g_wqkv_lo : g_wproj_lo;

    const int tid = threadIdx.x;
    const int wid = tid >> 5, l = tid & 31;
    const int bx = blockIdx.x, by = blockIdx.y;
    const int warp_m = wid & 3, warp_n = wid >> 2;

    if (tid < 128) sbias[tid] = bias[bx * 128 + tid];

    const uint32_t sb0 = smem_u32(dsm);
    const int lrow = tid >> 2, lseg = tid & 3;
    const __nv_bfloat16* srcs[4] = { Ahi, Alo, Whi, Wlo };
    const int rb_a = by * 128, rb_b = bx * 128;

    auto load_chunk = [&](int c, uint32_t sb) {
        #pragma unroll
        for (int t = 0; t < 4; ++t) {
            const __nv_bfloat16* src = srcs[t];
            const int rowbase = (t < 2) ? rb_a : rb_b;
            #pragma unroll
            for (int p = 0; p < 2; ++p) {
                const int r = lrow + p * 64;
                const void* gp = src + (size_t)(rowbase + r) * KDIM + c * 32 + lseg * 8;
                uint32_t sp = sb + t * TILE_B + (r * RSTRIDE + lseg * 8) * 2;
                asm volatile("cp.async.cg.shared.global [%0], [%1], 16;"
                             :: "r"(sp), "l"(gp) : "memory");
            }
        }
        asm volatile("cp.async.commit_group;" ::: "memory");
    };

    float acc[2][8][4];
    #pragma unroll
    for (int i = 0; i < 2; i++)
        #pragma unroll
        for (int j = 0; j < 8; j++)
            #pragma unroll
            for (int k = 0; k < 4; k++) acc[i][j][k] = 0.f;

    const int lm = l & 15, lkh = (l >> 4) * 8;
    const uint32_t a_off = ((warp_m * 32 + lm) * RSTRIDE + lkh) * 2;
    const uint32_t b_off = ((warp_n * 64 + lm) * RSTRIDE + lkh) * 2;

    load_chunk(0, sb0);

    const int NC = KDIM / 32;
    for (int c = 0; c < NC; ++c) {
        if (c + 1 < NC) {
            load_chunk(c + 1, sb0 + ((c + 1) & 1) * STAGE_B);
            asm volatile("cp.async.wait_group 1;" ::: "memory");
        } else {
            asm volatile("cp.async.wait_group 0;" ::: "memory");
        }
        __syncthreads();

        const uint32_t sb = sb0 + (c & 1) * STAGE_B;
        #pragma unroll
        for (int ks = 0; ks < 2; ++ks) {
            const uint32_t koff = ks * 32;
            uint32_t ah[2][4], al[2][4], bb[4][4];
            #pragma unroll
            for (int mf = 0; mf < 2; ++mf) {
                ldmx4(ah[mf], sb + a_off + mf * (16 * RSTRIDE * 2) + koff);
                ldmx4(al[mf], sb + TILE_B + a_off + mf * (16 * RSTRIDE * 2) + koff);
            }
            #pragma unroll
            for (int np = 0; np < 4; ++np)
                ldmx4(bb[np], sb + 2 * TILE_B + b_off + np * (16 * RSTRIDE * 2) + koff);
            // pass 1: hh — 16 MMAs, all-distinct accumulators
            #pragma unroll
            for (int mf = 0; mf < 2; ++mf)
                #pragma unroll
                for (int np = 0; np < 4; ++np) {
                    mma16816(acc[mf][2*np],   ah[mf], bb[np][0], bb[np][2]);
                    mma16816(acc[mf][2*np+1], ah[mf], bb[np][1], bb[np][3]);
                }
            // pass 2: lh — reuse distance ~15
            #pragma unroll
            for (int mf = 0; mf < 2; ++mf)
                #pragma unroll
                for (int np = 0; np < 4; ++np) {
                    mma16816(acc[mf][2*np],   al[mf], bb[np][0], bb[np][2]);
                    mma16816(acc[mf][2*np+1], al[mf], bb[np][1], bb[np][3]);
                }
            // pass 3: hl (Bl reuses bb regs)
            #pragma unroll
            for (int np = 0; np < 4; ++np)
                ldmx4(bb[np], sb + 3 * TILE_B + b_off + np * (16 * RSTRIDE * 2) + koff);
            #pragma unroll
            for (int mf = 0; mf < 2; ++mf)
                #pragma unroll
                for (int np = 0; np < 4; ++np) {
                    mma16816(acc[mf][2*np],   ah[mf], bb[np][0], bb[np][2]);
                    mma16816(acc[mf][2*np+1], ah[mf], bb[np][1], bb[np][3]);
                }
        }
        __syncthreads();
    }

    const int qr = l >> 2, qc = (l & 3) * 2;
    #pragma unroll
    for (int mf = 0; mf < 2; ++mf) {
        #pragma unroll
        for (int nt = 0; nt < 8; ++nt) {
            const int col = warp_n * 64 + nt * 8 + qc;
            const float b0 = sbias[col], b1 = sbias[col + 1];
            #pragma unroll
            for (int half = 0; half < 2; ++half) {
                const int row = warp_m * 32 + mf * 16 + qr + half * 8;
                const float vx = acc[mf][nt][2*half] + b0;
                const float vy = acc[mf][nt][2*half+1] + b1;
                const int m = by * 128 + row;
                if (MODE == 0) {
                    *(float2*)(out + (size_t)m * CH + bx * 128 + col) =
                        make_float2(vx, vy);
                } else {
                    const int cg = bx * 128 + col;
                    const int which = cg / CH;
                    const int rem = cg - which * CH;
                    const int h = rem >> 6, d0 = rem & 63;
                    const int b = m / SEQ, n = m - b * SEQ;
                    __nv_bfloat16* dh = (which == 0) ? g_qh : (which == 1) ? g_kh : g_vh;
                    __nv_bfloat16* dl = (which == 0) ? g_ql : (which == 1) ? g_kl : g_vl;
                    const size_t off = ((size_t)(b * HEADS + h) * SEQ + n) * HDIM + d0;
                    uint32_t hi, lo;
                    split2(vx, vy, hi, lo);
                    *(uint32_t*)(dh + off) = hi;
                    *(uint32_t*)(dl + off) = lo;
                }
            }
        }
    }
}

// ---------------------------------------------------------------------------
// Tensor-core flash attention. Block (qt,h,b), 128 thr = 4 warps x 16 q-rows.
// S and O MMAs issued in RAW-free passes (hh / lh / hl).
// ---------------------------------------------------------------------------
#define AROW  72
#define ATILE (64*AROW*2)     // 9216 B
#define ASMEM (6*ATILE)       // 55296 B

__global__ void __launch_bounds__(128) attn_mma()
{
    extern __shared__ char smbuf[];
    const uint32_t s0  = smem_u32(smbuf);
    const uint32_t sQh = s0,             sQl = s0 + ATILE;
    const uint32_t sKh = s0 + 2*ATILE,   sKl = s0 + 3*ATILE;
    const uint32_t sVh = s0 + 4*ATILE,   sVl = s0 + 5*ATILE;

    const int qt = blockIdx.x, h = blockIdx.y, b = blockIdx.z;
    const int tid = threadIdx.x;
    const int w = tid >> 5, l = tid & 31;

    const size_t head_off = (size_t)(b * HEADS + h) * SEQ * HDIM;
    const __nv_bfloat16* qhp = g_qh + head_off + (size_t)qt * 64 * HDIM;
    const __nv_bfloat16* qlp = g_ql + head_off + (size_t)qt * 64 * HDIM;
    const __nv_bfloat16* khp = g_kh + head_off;
    const __nv_bfloat16* klp = g_kl + head_off;
    const __nv_bfloat16* vhp = g_vh + head_off;
    const __nv_bfloat16* vlp = g_vl + head_off;

    #pragma unroll
    for (int it = 0; it < 4; ++it) {
        const int idx = tid + 128 * it;
        const int row = idx >> 3, seg = idx & 7;
        const uint32_t sp = row * 144 + seg * 16;
        const size_t gp = (size_t)row * HDIM + seg * 8;
        asm volatile("cp.async.cg.shared.global [%0], [%1], 16;"
                     :: "r"(sQh + sp), "l"(qhp + gp) : "memory");
        asm volatile("cp.async.cg.shared.global [%0], [%1], 16;"
                     :: "r"(sQl + sp), "l"(qlp + gp) : "memory");
    }
    auto load_kv = [&](int c) {
        #pragma unroll
        for (int it = 0; it < 4; ++it) {
            const int idx = tid + 128 * it;
            const int row = idx >> 3, seg = idx & 7;
            const uint32_t sp = row * 144 + seg * 16;
            const size_t gp = (size_t)(c * 64 + row) * HDIM + seg * 8;
            asm volatile("cp.async.cg.shared.global [%0], [%1], 16;"
                         :: "r"(sKh + sp), "l"(khp + gp) : "memory");
            asm volatile("cp.async.cg.shared.global [%0], [%1], 16;"
                         :: "r"(sKl + sp), "l"(klp + gp) : "memory");
            asm volatile("cp.async.cg.shared.global [%0], [%1], 16;"
                         :: "r"(sVh + sp), "l"(vhp + gp) : "memory");
            asm volatile("cp.async.cg.shared.global [%0], [%1], 16;"
                         :: "r"(sVl + sp), "l"(vlp + gp) : "memory");
        }
        asm volatile("cp.async.commit_group;" ::: "memory");
    };
    load_kv(0);
    asm volatile("cp.async.wait_group 0;" ::: "memory");
    __syncthreads();

    const int lm = l & 15, lk8 = (l >> 4) * 8;
    uint32_t qfh[4][4], qfl[4][4];
    #pragma unroll
    for (int ks = 0; ks < 4; ++ks) {
        const uint32_t off = (w * 16 + lm) * 144 + ks * 32 + lk8 * 2;
        ldmx4(qfh[ks], sQh + off);
        ldmx4(qfl[ks], sQl + off);
    }

    float m0 = -1e30f, m1 = -1e30f, l0 = 0.f, l1 = 0.f;
    float oacc[8][4];
    #pragma unroll
    for (int t = 0; t < 8; ++t)
        #pragma unroll
        for (int j = 0; j < 4; ++j) oacc[t][j] = 0.f;

    const int koff_t = ((l >> 3) & 1) * 8 + (l & 7);
    const int noff_t = ((l >> 4) & 1) * 8;

    const int nchunk = (qt == 0) ? 1 : 5;
    for (int c = 0; c < nchunk; ++c) {
        if (c > 0) {
            __syncthreads();
            load_kv(c);
            asm volatile("cp.async.wait_group 0;" ::: "memory");
            __syncthreads();
        }

        // ---- S = Q K^T : per ks, passes hh (8 distinct accs) / lh / hl --
        float sacc[8][4];
        #pragma unroll
        for (int t = 0; t < 8; ++t)
            #pragma unroll
            for (int j = 0; j < 4; ++j) sacc[t][j] = 0.f;

        #pragma unroll
        for (int ks = 0; ks < 4; ++ks) {
            uint32_t kbh[4][4], kbl[4][4];
            #pragma unroll
            for (int nt = 0; nt < 4; ++nt) {
                const uint32_t off = (nt * 16 + lm) * 144 + ks * 32 + lk8 * 2;
                ldmx4(kbh[nt], sKh + off);
                ldmx4(kbl[nt], sKl + off);
            }
            #pragma unroll
            for (int nt = 0; nt < 4; ++nt) {
                mma16816(sacc[2*nt],   qfh[ks], kbh[nt][0], kbh[nt][2]);
                mma16816(sacc[2*nt+1], qfh[ks], kbh[nt][1], kbh[nt][3]);
            }
            #pragma unroll
            for (int nt = 0; nt < 4; ++nt) {
                mma16816(sacc[2*nt],   qfl[ks], kbh[nt][0], kbh[nt][2]);
                mma16816(sacc[2*nt+1], qfl[ks], kbh[nt][1], kbh[nt][3]);
            }
            #pragma unroll
            for (int nt = 0; nt < 4; ++nt) {
                mma16816(sacc[2*nt],   qfh[ks], kbl[nt][0], kbl[nt][2]);
                mma16816(sacc[2*nt+1], qfh[ks], kbl[nt][1], kbl[nt][3]);
            }
        }

        // ---- softmax in fragment layout --------------------------------
        #pragma unroll
        for (int t = 0; t < 8; ++t)
            #pragma unroll
            for (int j = 0; j < 4; ++j) sacc[t][j] *= 0.125f;

        float mx0 = -1e30f, mx1 = -1e30f;
        #pragma unroll
        for (int t = 0; t < 8; ++t) {
            mx0 = fmaxf(mx0, fmaxf(sacc[t][0], sacc[t][1]));
            mx1 = fmaxf(mx1, fmaxf(sacc[t][2], sacc[t][3]));
        }
        mx0 = fmaxf(mx0, __shfl_xor_sync(0xffffffffu, mx0, 1));
        mx0 = fmaxf(mx0, __shfl_xor_sync(0xffffffffu, mx0, 2));
        mx1 = fmaxf(mx1, __shfl_xor_sync(0xffffffffu, mx1, 1));
        mx1 = fmaxf(mx1, __shfl_xor_sync(0xffffffffu, mx1, 2));

        const float mn0 = fmaxf(m0, mx0), mn1 = fmaxf(m1, mx1);
        const float cr0 = __expf(m0 - mn0), cr1 = __expf(m1 - mn1);
        m0 = mn0; m1 = mn1;

        float sm0 = 0.f, sm1 = 0.f;
        #pragma unroll
        for (int t = 0; t < 8; ++t) {
            sacc[t][0] = __expf(sacc[t][0] - mn0);
            sacc[t][1] = __expf(sacc[t][1] - mn0);
            sacc[t][2] = __expf(sacc[t][2] - mn1);
            sacc[t][3] = __expf(sacc[t][3] - mn1);
            sm0 += sacc[t][0] + sacc[t][1];
            sm1 += sacc[t][2] + sacc[t][3];
        }
        sm0 += __shfl_xor_sync(0xffffffffu, sm0, 1);
        sm0 += __shfl_xor_sync(0xffffffffu, sm0, 2);
        sm1 += __shfl_xor_sync(0xffffffffu, sm1, 1);
        sm1 += __shfl_xor_sync(0xffffffffu, sm1, 2);
        l0 = l0 * cr0 + sm0;
        l1 = l1 * cr1 + sm1;

        #pragma unroll
        for (int t = 0; t < 8; ++t) {
            oacc[t][0] *= cr0; oacc[t][1] *= cr0;
            oacc[t][2] *= cr1; oacc[t][3] *= cr1;
        }

        // ---- O += P V : per ks, passes hh / lh / hl --------------------
        #pragma unroll
        for (int ks = 0; ks < 4; ++ks) {
            uint32_t pah[4], pal[4];
            split2(sacc[2*ks][0],   sacc[2*ks][1],   pah[0], pal[0]);
            split2(sacc[2*ks][2],   sacc[2*ks][3],   pah[1], pal[1]);
            split2(sacc[2*ks+1][0], sacc[2*ks+1][1], pah[2], pal[2]);
            split2(sacc[2*ks+1][2], sacc[2*ks+1][3], pah[3], pal[3]);

            uint32_t vbh[4][4], vbl[4][4];
            #pragma unroll
            for (int nd = 0; nd < 4; ++nd) {
                const uint32_t off = (ks * 16 + koff_t) * 144
                                   + (nd * 16 + noff_t) * 2;
                ldmx4t(vbh[nd], sVh + off);
                ldmx4t(vbl[nd], sVl + off);
            }
            #pragma unroll
            for (int nd = 0; nd < 4; ++nd) {
                mma16816(oacc[2*nd],   pah, vbh[nd][0], vbh[nd][1]);
                mma16816(oacc[2*nd+1], pah, vbh[nd][2], vbh[nd][3]);
            }
            #pragma unroll
            for (int nd = 0; nd < 4; ++nd) {
                mma16816(oacc[2*nd],   pal, vbh[nd][0], vbh[nd][1]);
                mma16816(oacc[2*nd+1], pal, vbh[nd][2], vbh[nd][3]);
            }
            #pragma unroll
            for (int nd = 0; nd < 4; ++nd) {
                mma16816(oacc[2*nd],   pah, vbl[nd][0], vbl[nd][1]);
                mma16816(oacc[2*nd+1], pah, vbl[nd][2], vbl[nd][3]);
            }
        }
    }

    const float inv0 = 1.0f / l0, inv1 = 1.0f / l1;
    const int n0 = qt * 64 + w * 16 + (l >> 2);
    const int n1 = n0 + 8;
    const size_t row0 = ((size_t)b * SEQ + n0) * CH + h * HDIM;
    const size_t row1 = ((size_t)b * SEQ + n1) * CH + h * HDIM;
    #pragma unroll
    for (int t = 0; t < 8; ++t) {
        const int d0 = t * 8 + (l & 3) * 2;
        uint32_t hi, lo;
        split2(oacc[t][0] * inv0, oacc[t][1] * inv0, hi, lo);
        *(uint32_t*)(g_att_hi + row0 + d0) = hi;
        *(uint32_t*)(g_att_lo + row0 + d0) = lo;
        split2(oacc[t][2] * inv1, oacc[t][3] * inv1, hi, lo);
        *(uint32_t*)(g_att_hi + row1 + d0) = hi;
        *(uint32_t*)(g_att_lo + row1 + d0) = lo;
    }
}

// ---------------------------------------------------------------------------
extern "C" void kernel_launch(void* const* d_in, const int* in_sizes, int n_in,
                              void* d_out, int out_size)
{
    const float* x      = (const float*)d_in[0];
    const float* w_qkv  = (const float*)d_in[1];
    const float* b_qkv  = (const float*)d_in[2];
    const float* w_proj = (const float*)d_in[3];
    const float* b_proj = (const float*)d_in[4];
    float* out = (float*)d_out;
    (void)in_sizes; (void)n_in; (void)out_size;

    cudaFuncSetAttribute(gemm_mma<1>, cudaFuncAttributeMaxDynamicSharedMemorySize, SMEM_DYN);
    cudaFuncSetAttribute(gemm_mma<0>, cudaFuncAttributeMaxDynamicSharedMemorySize, SMEM_DYN);
    cudaFuncSetAttribute(attn_mma, cudaFuncAttributeMaxDynamicSharedMemorySize, ASMEM);

    {   // fp32 -> bf16 hi/lo splits
        int n4 = MROWS * KDIM / 4;
        cvt_split<0><<<(n4 + 255) / 256, 256>>>(x, n4);
        n4 = 3 * CH * KDIM / 4;
        cvt_split<1><<<(n4 + 255) / 256, 256>>>(w_qkv, n4);
        n4 = CH * KDIM / 4;
        cvt_split<2><<<(n4 + 255) / 256, 256>>>(w_proj, n4);
    }

    gemm_mma<1><<<dim3(3 * CH / 128, MROWS / 128), 256, SMEM_DYN>>>(b_qkv, nullptr);
    attn_mma<<<dim3(5, HEADS, BATCH), 128, ASMEM>>>();
    gemm_mma<0><<<dim3(CH / 128, MROWS / 128), 256, SMEM_DYN>>>(b_proj, out);
}

// round 15
// speedup vs baseline: 2.5507x; 1.0036x over previous
#include <cuda_runtime.h>
#include <cuda_bf16.h>
#include <cstdint>

#define BATCH 64
#define SEQ   320
#define CH    768
#define HEADS 12
#define HDIM  64
#define KDIM  768
#define MROWS (BATCH*SEQ)   // 20480

// ---------------- device global scratch (allocation-free rule) --------------
__device__ __nv_bfloat16 g_qh[(size_t)BATCH*HEADS*SEQ*HDIM];
__device__ __nv_bfloat16 g_ql[(size_t)BATCH*HEADS*SEQ*HDIM];
__device__ __nv_bfloat16 g_kh[(size_t)BATCH*HEADS*SEQ*HDIM];
__device__ __nv_bfloat16 g_kl[(size_t)BATCH*HEADS*SEQ*HDIM];
__device__ __nv_bfloat16 g_vh[(size_t)BATCH*HEADS*SEQ*HDIM];
__device__ __nv_bfloat16 g_vl[(size_t)BATCH*HEADS*SEQ*HDIM];
__device__ __nv_bfloat16 g_xhi[(size_t)MROWS*KDIM];
__device__ __nv_bfloat16 g_xlo[(size_t)MROWS*KDIM];
__device__ __nv_bfloat16 g_wqkv_hi[(size_t)3*CH*KDIM];
__device__ __nv_bfloat16 g_wqkv_lo[(size_t)3*CH*KDIM];
__device__ __nv_bfloat16 g_wproj_hi[(size_t)CH*KDIM];
__device__ __nv_bfloat16 g_wproj_lo[(size_t)CH*KDIM];
__device__ __nv_bfloat16 g_att_hi[(size_t)MROWS*CH];
__device__ __nv_bfloat16 g_att_lo[(size_t)MROWS*CH];

// ---------------- helpers ---------------------------------------------------
__device__ __forceinline__ uint32_t smem_u32(const void* p) {
    uint32_t a;
    asm("{ .reg .u64 t; cvta.to.shared.u64 t, %1; cvt.u32.u64 %0, t; }"
        : "=r"(a) : "l"(p));
    return a;
}
__device__ __forceinline__ void ldmx4(uint32_t* r, uint32_t addr) {
    asm volatile("ldmatrix.sync.aligned.m8n8.x4.shared.b16 {%0,%1,%2,%3}, [%4];"
        : "=r"(r[0]), "=r"(r[1]), "=r"(r[2]), "=r"(r[3]) : "r"(addr));
}
__device__ __forceinline__ void ldmx4t(uint32_t* r, uint32_t addr) {
    asm volatile("ldmatrix.sync.aligned.m8n8.x4.trans.shared.b16 {%0,%1,%2,%3}, [%4];"
        : "=r"(r[0]), "=r"(r[1]), "=r"(r[2]), "=r"(r[3]) : "r"(addr));
}
__device__ __forceinline__ void mma16816(float* c, const uint32_t* a,
                                         uint32_t b0, uint32_t b1) {
    asm volatile("mma.sync.aligned.m16n8k16.row.col.f32.bf16.bf16.f32 "
        "{%0,%1,%2,%3}, {%4,%5,%6,%7}, {%8,%9}, {%0,%1,%2,%3};"
        : "+f"(c[0]), "+f"(c[1]), "+f"(c[2]), "+f"(c[3])
        : "r"(a[0]), "r"(a[1]), "r"(a[2]), "r"(a[3]), "r"(b0), "r"(b1));
}
__device__ __forceinline__ uint32_t pack_bf2(__nv_bfloat16 a, __nv_bfloat16 b) {
    return ((uint32_t)__bfloat16_as_ushort(b) << 16) | (uint32_t)__bfloat16_as_ushort(a);
}
__device__ __forceinline__ void split2(float x, float y, uint32_t& hi, uint32_t& lo) {
    __nv_bfloat16 hx = __float2bfloat16(x), hy = __float2bfloat16(y);
    hi = pack_bf2(hx, hy);
    lo = pack_bf2(__float2bfloat16(x - __bfloat162float(hx)),
                  __float2bfloat16(y - __bfloat162float(hy)));
}

// ---------------- fp32 -> bf16 hi/lo split ----------------------------------
template<int T>
__global__ void cvt_split(const float* __restrict__ s, int n4) {
    __nv_bfloat16* hi = (T == 0) ? g_xhi : (T == 1) ? g_wqkv_hi : g_wproj_hi;
    __nv_bfloat16* lo = (T == 0) ? g_xlo : (T == 1) ? g_wqkv_lo : g_wproj_lo;
    int i = blockIdx.x * blockDim.x + threadIdx.x;
    if (i >= n4) return;
    float4 v = ((const float4*)s)[i];
    uint32_t h0, l0, h1, l1;
    split2(v.x, v.y, h0, l0);
    split2(v.z, v.w, h1, l1);
    ((uint2*)hi)[i] = make_uint2(h0, h1);
    ((uint2*)lo)[i] = make_uint2(l0, l1);
}

// ---------------------------------------------------------------------------
// bf16-split warp-MMA GEMM. 128x128 tile, 8 warps (4m x 2n), warp tile 32x64.
// BK=32, double-buffered cp.async, ONE __syncthreads per chunk:
//   wait(c) -> barrier -> prefetch(c+1) -> compute(c)
// RSTRIDE=40 (80B rows): 16B-aligned for cp.async, conflict-free for ldmatrix.
// MODE 1: A=x(split), W=wqkv(split), epilogue splits to bf16 -> g_{q,k,v}{h,l}.
// MODE 0: A=att(split), W=wproj(split), out[m*CH+n] fp32.
// ---------------------------------------------------------------------------
#define RSTRIDE 40
#define TILE_B  (128*RSTRIDE*2)     // 10240 B
#define STAGE_B (4*TILE_B)          // 40960 B
#define SMEM_DYN (2*STAGE_B)        // 81920 B

template<int MODE>
__global__ void __launch_bounds__(256, 2)
gemm_mma(const float* __restrict__ bias, float* __restrict__ out)
{
    extern __shared__ char dsm[];
    __shared__ float sbias[128];

    const __nv_bfloat16* Ahi = (MODE == 1) ? g_xhi : g_att_hi;
    const __nv_bfloat16* Alo = (MODE == 1) ? g_xlo : g_att_lo;
    const __nv_bfloat16* Whi = (MODE == 1) ? g_wqkv_hi : g_wproj_hi;
    const __nv_bfloat16* Wlo = (MODE == 1) ? g_wqkv_lo : g_wproj_lo;

    const int tid = threadIdx.x;
    const int wid = tid >> 5, l = tid & 31;
    const int bx = blockIdx.x, by = blockIdx.y;
    const int warp_m = wid & 3, warp_n = wid >> 2;

    if (tid < 128) sbias[tid] = bias[bx * 128 + tid];

    const uint32_t sb0 = smem_u32(dsm);
    const int lrow = tid >> 2, lseg = tid & 3;
    const __nv_bfloat16* srcs[4] = { Ahi, Alo, Whi, Wlo };
    const int rb_a = by * 128, rb_b = bx * 128;

    auto load_chunk = [&](int c) {
        const uint32_t sb = sb0 + (c & 1) * STAGE_B;
        #pragma unroll
        for (int t = 0; t < 4; ++t) {
            const __nv_bfloat16* src = srcs[t];
            const int rowbase = (t < 2) ? rb_a : rb_b;
            #pragma unroll
            for (int p = 0; p < 2; ++p) {
                const int r = lrow + p * 64;
                const void* gp = src + (size_t)(rowbase + r) * KDIM + c * 32 + lseg * 8;
                uint32_t sp = sb + t * TILE_B + (r * RSTRIDE + lseg * 8) * 2;
                asm volatile("cp.async.cg.shared.global [%0], [%1], 16;"
                             :: "r"(sp), "l"(gp) : "memory");
            }
        }
        asm volatile("cp.async.commit_group;" ::: "memory");
    };

    float acc[2][8][4];
    #pragma unroll
    for (int i = 0; i < 2; i++)
        #pragma unroll
        for (int j = 0; j < 8; j++)
            #pragma unroll
            for (int k = 0; k < 4; k++) acc[i][j][k] = 0.f;

    const int lm = l & 15, lkh = (l >> 4) * 8;
    const uint32_t a_off = ((warp_m * 32 + lm) * RSTRIDE + lkh) * 2;
    const uint32_t b_off = ((warp_n * 64 + lm) * RSTRIDE + lkh) * 2;

    load_chunk(0);

    const int NC = KDIM / 32;   // 24
    for (int c = 0; c < NC; ++c) {
        asm volatile("cp.async.wait_group 0;" ::: "memory");   // chunk c resident
        __syncthreads();   // publish chunk c; retire iter c-1 readers of buf (c+1)&1

        if (c + 1 < NC) load_chunk(c + 1);   // overlaps with compute below

        const uint32_t sb = sb0 + (c & 1) * STAGE_B;
        #pragma unroll
        for (int ks = 0; ks < 2; ++ks) {
            const uint32_t koff = ks * 32;
            uint32_t ah[2][4], al[2][4], bb[4][4];
            #pragma unroll
            for (int mf = 0; mf < 2; ++mf) {
                ldmx4(ah[mf], sb + a_off + mf * (16 * RSTRIDE * 2) + koff);
                ldmx4(al[mf], sb + TILE_B + a_off + mf * (16 * RSTRIDE * 2) + koff);
            }
            #pragma unroll
            for (int np = 0; np < 4; ++np)
                ldmx4(bb[np], sb + 2 * TILE_B + b_off + np * (16 * RSTRIDE * 2) + koff);
            #pragma unroll
            for (int mf = 0; mf < 2; ++mf)
                #pragma unroll
                for (int np = 0; np < 4; ++np) {
                    mma16816(acc[mf][2*np],   ah[mf], bb[np][0], bb[np][2]);
                    mma16816(acc[mf][2*np+1], ah[mf], bb[np][1], bb[np][3]);
                }
            #pragma unroll
            for (int mf = 0; mf < 2; ++mf)
                #pragma unroll
                for (int np = 0; np < 4; ++np) {
                    mma16816(acc[mf][2*np],   al[mf], bb[np][0], bb[np][2]);
                    mma16816(acc[mf][2*np+1], al[mf], bb[np][1], bb[np][3]);
                }
            #pragma unroll
            for (int np = 0; np < 4; ++np)
                ldmx4(bb[np], sb + 3 * TILE_B + b_off + np * (16 * RSTRIDE * 2) + koff);
            #pragma unroll
            for (int mf = 0; mf < 2; ++mf)
                #pragma unroll
                for (int np = 0; np < 4; ++np) {
                    mma16816(acc[mf][2*np],   ah[mf], bb[np][0], bb[np][2]);
                    mma16816(acc[mf][2*np+1], ah[mf], bb[np][1], bb[np][3]);
                }
        }
    }

    const int qr = l >> 2, qc = (l & 3) * 2;
    #pragma unroll
    for (int mf = 0; mf < 2; ++mf) {
        #pragma unroll
        for (int nt = 0; nt < 8; ++nt) {
            const int col = warp_n * 64 + nt * 8 + qc;
            const float b0 = sbias[col], b1 = sbias[col + 1];
            #pragma unroll
            for (int half = 0; half < 2; ++half) {
                const int row = warp_m * 32 + mf * 16 + qr + half * 8;
                const float vx = acc[mf][nt][2*half] + b0;
                const float vy = acc[mf][nt][2*half+1] + b1;
                const int m = by * 128 + row;
                if (MODE == 0) {
                    *(float2*)(out + (size_t)m * CH + bx * 128 + col) =
                        make_float2(vx, vy);
                } else {
                    const int cg = bx * 128 + col;
                    const int which = cg / CH;
                    const int rem = cg - which * CH;
                    const int h = rem >> 6, d0 = rem & 63;
                    const int b = m / SEQ, n = m - b * SEQ;
                    __nv_bfloat16* dh = (which == 0) ? g_qh : (which == 1) ? g_kh : g_vh;
                    __nv_bfloat16* dl = (which == 0) ? g_ql : (which == 1) ? g_kl : g_vl;
                    const size_t off = ((size_t)(b * HEADS + h) * SEQ + n) * HDIM + d0;
                    uint32_t hi, lo;
                    split2(vx, vy, hi, lo);
                    *(uint32_t*)(dh + off) = hi;
                    *(uint32_t*)(dl + off) = lo;
                }
            }
        }
    }
}

// ---------------------------------------------------------------------------
// Tensor-core flash attention (unchanged from the 1108us passing version).
// ---------------------------------------------------------------------------
#define AROW  72
#define ATILE (64*AROW*2)     // 9216 B
#define ASMEM (6*ATILE)       // 55296 B

__global__ void __launch_bounds__(128) attn_mma()
{
    extern __shared__ char smbuf[];
    const uint32_t s0  = smem_u32(smbuf);
    const uint32_t sQh = s0,             sQl = s0 + ATILE;
    const uint32_t sKh = s0 + 2*ATILE,   sKl = s0 + 3*ATILE;
    const uint32_t sVh = s0 + 4*ATILE,   sVl = s0 + 5*ATILE;

    const int qt = blockIdx.x, h = blockIdx.y, b = blockIdx.z;
    const int tid = threadIdx.x;
    const int w = tid >> 5, l = tid & 31;

    const size_t head_off = (size_t)(b * HEADS + h) * SEQ * HDIM;
    const __nv_bfloat16* qhp = g_qh + head_off + (size_t)qt * 64 * HDIM;
    const __nv_bfloat16* qlp = g_ql + head_off + (size_t)qt * 64 * HDIM;
    const __nv_bfloat16* khp = g_kh + head_off;
    const __nv_bfloat16* klp = g_kl + head_off;
    const __nv_bfloat16* vhp = g_vh + head_off;
    const __nv_bfloat16* vlp = g_vl + head_off;

    #pragma unroll
    for (int it = 0; it < 4; ++it) {
        const int idx = tid + 128 * it;
        const int row = idx >> 3, seg = idx & 7;
        const uint32_t sp = row * 144 + seg * 16;
        const size_t gp = (size_t)row * HDIM + seg * 8;
        asm volatile("cp.async.cg.shared.global [%0], [%1], 16;"
                     :: "r"(sQh + sp), "l"(qhp + gp) : "memory");
        asm volatile("cp.async.cg.shared.global [%0], [%1], 16;"
                     :: "r"(sQl + sp), "l"(qlp + gp) : "memory");
    }
    auto load_kv = [&](int c) {
        #pragma unroll
        for (int it = 0; it < 4; ++it) {
            const int idx = tid + 128 * it;
            const int row = idx >> 3, seg = idx & 7;
            const uint32_t sp = row * 144 + seg * 16;
            const size_t gp = (size_t)(c * 64 + row) * HDIM + seg * 8;
            asm volatile("cp.async.cg.shared.global [%0], [%1], 16;"
                         :: "r"(sKh + sp), "l"(khp + gp) : "memory");
            asm volatile("cp.async.cg.shared.global [%0], [%1], 16;"
                         :: "r"(sKl + sp), "l"(klp + gp) : "memory");
            asm volatile("cp.async.cg.shared.global [%0], [%1], 16;"
                         :: "r"(sVh + sp), "l"(vhp + gp) : "memory");
            asm volatile("cp.async.cg.shared.global [%0], [%1], 16;"
                         :: "r"(sVl + sp), "l"(vlp + gp) : "memory");
        }
        asm volatile("cp.async.commit_group;" ::: "memory");
    };
    load_kv(0);
    asm volatile("cp.async.wait_group 0;" ::: "memory");
    __syncthreads();

    const int lm = l & 15, lk8 = (l >> 4) * 8;
    uint32_t qfh[4][4], qfl[4][4];
    #pragma unroll
    for (int ks = 0; ks < 4; ++ks) {
        const uint32_t off = (w * 16 + lm) * 144 + ks * 32 + lk8 * 2;
        ldmx4(qfh[ks], sQh + off);
        ldmx4(qfl[ks], sQl + off);
    }

    float m0 = -1e30f, m1 = -1e30f, l0 = 0.f, l1 = 0.f;
    float oacc[8][4];
    #pragma unroll
    for (int t = 0; t < 8; ++t)
        #pragma unroll
        for (int j = 0; j < 4; ++j) oacc[t][j] = 0.f;

    const int koff_t = ((l >> 3) & 1) * 8 + (l & 7);
    const int noff_t = ((l >> 4) & 1) * 8;

    const int nchunk = (qt == 0) ? 1 : 5;
    for (int c = 0; c < nchunk; ++c) {
        if (c > 0) {
            __syncthreads();
            load_kv(c);
            asm volatile("cp.async.wait_group 0;" ::: "memory");
            __syncthreads();
        }

        float sacc[8][4];
        #pragma unroll
        for (int t = 0; t < 8; ++t)
            #pragma unroll
            for (int j = 0; j < 4; ++j) sacc[t][j] = 0.f;

        #pragma unroll
        for (int ks = 0; ks < 4; ++ks) {
            uint32_t kbh[4][4], kbl[4][4];
            #pragma unroll
            for (int nt = 0; nt < 4; ++nt) {
                const uint32_t off = (nt * 16 + lm) * 144 + ks * 32 + lk8 * 2;
                ldmx4(kbh[nt], sKh + off);
                ldmx4(kbl[nt], sKl + off);
            }
            #pragma unroll
            for (int nt = 0; nt < 4; ++nt) {
                mma16816(sacc[2*nt],   qfh[ks], kbh[nt][0], kbh[nt][2]);
                mma16816(sacc[2*nt+1], qfh[ks], kbh[nt][1], kbh[nt][3]);
            }
            #pragma unroll
            for (int nt = 0; nt < 4; ++nt) {
                mma16816(sacc[2*nt],   qfl[ks], kbh[nt][0], kbh[nt][2]);
                mma16816(sacc[2*nt+1], qfl[ks], kbh[nt][1], kbh[nt][3]);
            }
            #pragma unroll
            for (int nt = 0; nt < 4; ++nt) {
                mma16816(sacc[2*nt],   qfh[ks], kbl[nt][0], kbl[nt][2]);
                mma16816(sacc[2*nt+1], qfh[ks], kbl[nt][1], kbl[nt][3]);
            }
        }

        #pragma unroll
        for (int t = 0; t < 8; ++t)
            #pragma unroll
            for (int j = 0; j < 4; ++j) sacc[t][j] *= 0.125f;

        float mx0 = -1e30f, mx1 = -1e30f;
        #pragma unroll
        for (int t = 0; t < 8; ++t) {
            mx0 = fmaxf(mx0, fmaxf(sacc[t][0], sacc[t][1]));
            mx1 = fmaxf(mx1, fmaxf(sacc[t][2], sacc[t][3]));
        }
        mx0 = fmaxf(mx0, __shfl_xor_sync(0xffffffffu, mx0, 1));
        mx0 = fmaxf(mx0, __shfl_xor_sync(0xffffffffu, mx0, 2));
        mx1 = fmaxf(mx1, __shfl_xor_sync(0xffffffffu, mx1, 1));
        mx1 = fmaxf(mx1, __shfl_xor_sync(0xffffffffu, mx1, 2));

        const float mn0 = fmaxf(m0, mx0), mn1 = fmaxf(m1, mx1);
        const float cr0 = __expf(m0 - mn0), cr1 = __expf(m1 - mn1);
        m0 = mn0; m1 = mn1;

        float sm0 = 0.f, sm1 = 0.f;
        #pragma unroll
        for (int t = 0; t < 8; ++t) {
            sacc[t][0] = __expf(sacc[t][0] - mn0);
            sacc[t][1] = __expf(sacc[t][1] - mn0);
            sacc[t][2] = __expf(sacc[t][2] - mn1);
            sacc[t][3] = __expf(sacc[t][3] - mn1);
            sm0 += sacc[t][0] + sacc[t][1];
            sm1 += sacc[t][2] + sacc[t][3];
        }
        sm0 += __shfl_xor_sync(0xffffffffu, sm0, 1);
        sm0 += __shfl_xor_sync(0xffffffffu, sm0, 2);
        sm1 += __shfl_xor_sync(0xffffffffu, sm1, 1);
        sm1 += __shfl_xor_sync(0xffffffffu, sm1, 2);
        l0 = l0 * cr0 + sm0;
        l1 = l1 * cr1 + sm1;

        #pragma unroll
        for (int t = 0; t < 8; ++t) {
            oacc[t][0] *= cr0; oacc[t][1] *= cr0;
            oacc[t][2] *= cr1; oacc[t][3] *= cr1;
        }

        #pragma unroll
        for (int ks = 0; ks < 4; ++ks) {
            uint32_t pah[4], pal[4];
            split2(sacc[2*ks][0],   sacc[2*ks][1],   pah[0], pal[0]);
            split2(sacc[2*ks][2],   sacc[2*ks][3],   pah[1], pal[1]);
            split2(sacc[2*ks+1][0], sacc[2*ks+1][1], pah[2], pal[2]);
            split2(sacc[2*ks+1][2], sacc[2*ks+1][3], pah[3], pal[3]);

            uint32_t vbh[4][4], vbl[4][4];
            #pragma unroll
            for (int nd = 0; nd < 4; ++nd) {
                const uint32_t off = (ks * 16 + koff_t) * 144
                                   + (nd * 16 + noff_t) * 2;
                ldmx4t(vbh[nd], sVh + off);
                ldmx4t(vbl[nd], sVl + off);
            }
            #pragma unroll
            for (int nd = 0; nd < 4; ++nd) {
                mma16816(oacc[2*nd],   pah, vbh[nd][0], vbh[nd][1]);
                mma16816(oacc[2*nd+1], pah, vbh[nd][2], vbh[nd][3]);
            }
            #pragma unroll
            for (int nd = 0; nd < 4; ++nd) {
                mma16816(oacc[2*nd],   pal, vbh[nd][0], vbh[nd][1]);
                mma16816(oacc[2*nd+1], pal, vbh[nd][2], vbh[nd][3]);
            }
            #pragma unroll
            for (int nd = 0; nd < 4; ++nd) {
                mma16816(oacc[2*nd],   pah, vbl[nd][0], vbl[nd][1]);
                mma16816(oacc[2*nd+1], pah, vbl[nd][2], vbl[nd][3]);
            }
        }
    }

    const float inv0 = 1.0f / l0, inv1 = 1.0f / l1;
    const int n0 = qt * 64 + w * 16 + (l >> 2);
    const int n1 = n0 + 8;
    const size_t row0 = ((size_t)b * SEQ + n0) * CH + h * HDIM;
    const size_t row1 = ((size_t)b * SEQ + n1) * CH + h * HDIM;
    #pragma unroll
    for (int t = 0; t < 8; ++t) {
        const int d0 = t * 8 + (l & 3) * 2;
        uint32_t hi, lo;
        split2(oacc[t][0] * inv0, oacc[t][1] * inv0, hi, lo);
        *(uint32_t*)(g_att_hi + row0 + d0) = hi;
        *(uint32_t*)(g_att_lo + row0 + d0) = lo;
        split2(oacc[t][2] * inv1, oacc[t][3] * inv1, hi, lo);
        *(uint32_t*)(g_att_hi + row1 + d0) = hi;
        *(uint32_t*)(g_att_lo + row1 + d0) = lo;
    }
}

// ---------------------------------------------------------------------------
extern "C" void kernel_launch(void* const* d_in, const int* in_sizes, int n_in,
                              void* d_out, int out_size)
{
    const float* x      = (const float*)d_in[0];
    const float* w_qkv  = (const float*)d_in[1];
    const float* b_qkv  = (const float*)d_in[2];
    const float* w_proj = (const float*)d_in[3];
    const float* b_proj = (const float*)d_in[4];
    float* out = (float*)d_out;
    (void)in_sizes; (void)n_in; (void)out_size;

    cudaFuncSetAttribute(gemm_mma<1>, cudaFuncAttributeMaxDynamicSharedMemorySize, SMEM_DYN);
    cudaFuncSetAttribute(gemm_mma<0>, cudaFuncAttributeMaxDynamicSharedMemorySize, SMEM_DYN);
    cudaFuncSetAttribute(attn_mma, cudaFuncAttributeMaxDynamicSharedMemorySize, ASMEM);

    {   // fp32 -> bf16 hi/lo splits
        int n4 = MROWS * KDIM / 4;
        cvt_split<0><<<(n4 + 255) / 256, 256>>>(x, n4);
        n4 = 3 * CH * KDIM / 4;
        cvt_split<1><<<(n4 + 255) / 256, 256>>>(w_qkv, n4);
        n4 = CH * KDIM / 4;
        cvt_split<2><<<(n4 + 255) / 256, 256>>>(w_proj, n4);
    }

    gemm_mma<1><<<dim3(3 * CH / 128, MROWS / 128), 256, SMEM_DYN>>>(b_qkv, nullptr);
    attn_mma<<<dim3(5, HEADS, BATCH), 128, ASMEM>>>();
    gemm_mma<0><<<dim3(CH / 128, MROWS / 128), 256, SMEM_DYN>>>(b_proj, out);
}